// round 11
// baseline (speedup 1.0000x reference)
#include <cuda_runtime.h>
#include <cuda_fp16.h>
#include <cstdint>

#define B_GRAPHS 64
#define NODES_PER_G 1600
#define N_NODES (B_GRAPHS * NODES_PER_G)   // 102400
#define F_DIM 128
#define K_CL 16
#define E_EDGES (N_NODES * 32)             // 3276800
#define SPLIT_A 16
#define NPART_A (NODES_PER_G / SPLIT_A)    // 100
#define CHUNK_A 20
#define EDGE_BLOCKS (E_EDGES / 512)        // 6400
#define ADJ_BLOCKS (B_GRAPHS * SPLIT_A)    // 1024
#define OX_BLOCKS B_GRAPHS                 // 64, one per graph

// ---------------- device scratch ----------------
__device__ __align__(16) float g_s[N_NODES * K_CL];      // fp32 s (6.55 MB)
__device__ __align__(32) __half g_sh[N_NODES * K_CL];    // fp16 s copy (3.28 MB)
__device__ __align__(32) __half g_Mh[N_NODES * K_CL];    // fp16 M accumulator (3.28 MB)
__device__ float g_adj[B_GRAPHS * K_CL * K_CL];
__device__ float g_cc[B_GRAPHS * K_CL * K_CL];
__device__ float g_num;
__device__ float g_den;
__device__ float g_ortho;
__device__ unsigned int g_cnt;
__device__ unsigned int g_cnt_adj[B_GRAPHS];

// ---------------- helpers ----------------
__device__ __forceinline__ void red1(float* p, float a) {
    asm volatile("red.global.add.f32 [%0], %1;" :: "l"(p), "f"(a) : "memory");
}
__device__ __forceinline__ void red4h(__half* p, uint32_t r0, uint32_t r1,
                                      uint32_t r2, uint32_t r3) {
    asm volatile("red.global.add.noftz.v4.f16x2 [%0], {%1,%2,%3,%4};"
                 :: "l"(p), "r"(r0), "r"(r1), "r"(r2), "r"(r3) : "memory");
}
__device__ __forceinline__ __half2 u2h(uint32_t v) { return *(__half2*)&v; }
__device__ __forceinline__ uint32_t h2m(uint32_t v, __half2 w) {
    __half2 h = __hmul2(u2h(v), w);
    return *(uint32_t*)&h;
}
__device__ __forceinline__ float ssq16(uint4 a, uint4 b) {
    __half2 q = __hmul2(u2h(a.x), u2h(a.x));
    q = __hfma2(u2h(a.y), u2h(a.y), q);
    q = __hfma2(u2h(a.z), u2h(a.z), q);
    q = __hfma2(u2h(a.w), u2h(a.w), q);
    q = __hfma2(u2h(b.x), u2h(b.x), q);
    q = __hfma2(u2h(b.y), u2h(b.y), q);
    q = __hfma2(u2h(b.z), u2h(b.z), q);
    q = __hfma2(u2h(b.w), u2h(b.w), q);
    float2 f = __half22float2(q);
    return f.x + f.y;
}

__device__ __forceinline__ float selu_f(float v) {
    const float scale = 1.0507009873554805f;
    const float alpha = 1.6732632423543772f;
    return v > 0.f ? scale * v : scale * alpha * (__expf(v) - 1.f);
}

__device__ __forceinline__ float grp16_sum(float v) {
    v += __shfl_xor_sync(0xffffffffu, v, 1);
    v += __shfl_xor_sync(0xffffffffu, v, 2);
    v += __shfl_xor_sync(0xffffffffu, v, 4);
    v += __shfl_xor_sync(0xffffffffu, v, 8);
    return v;
}

__device__ __forceinline__ float blockSum256s(float v, volatile float* sh8) {
    int t = threadIdx.x;
    #pragma unroll
    for (int d = 16; d > 0; d >>= 1) v += __shfl_xor_sync(0xffffffffu, v, d);
    if ((t & 31) == 0) sh8[t >> 5] = v;
    __syncthreads();
    float r = sh8[0] + sh8[1] + sh8[2] + sh8[3] + sh8[4] + sh8[5] + sh8[6] + sh8[7];
    __syncthreads();
    return r;
}

// ---------------- K1: s = softmax^2(xW+b), 4 nodes/warp + zeroing ---------
__global__ void __launch_bounds__(256) k_s(const float* __restrict__ x,
                                           const float* __restrict__ W,
                                           const float* __restrict__ bvec) {
    __shared__ float sWT[K_CL][132];
    __shared__ float xs[8][4][F_DIM];
    int t = threadIdx.x;
    int bid = blockIdx.x;                 // grid = 3200

    if (t < 64) ((uint4*)g_Mh)[bid * 64 + t] = make_uint4(0u,0u,0u,0u);
    if (bid < 16) {
        int i = bid * 256 + t;
        ((float4*)g_adj)[i] = make_float4(0.f,0.f,0.f,0.f);
        ((float4*)g_cc)[i]  = make_float4(0.f,0.f,0.f,0.f);
    }
    if (bid == 0) {
        if (t < B_GRAPHS) g_cnt_adj[t] = 0u;
        if (t == 0) { g_num = 0.f; g_den = 0.f; g_ortho = 0.f; g_cnt = 0u; }
    }

    for (int i = t; i < F_DIM * K_CL; i += 256) {
        int j = i >> 4, k = i & 15;
        sWT[k][j] = W[i];
    }
    __syncthreads();

    int w = t >> 5, l = t & 31;
    int node0 = bid * 32 + w * 4;
    int k = l & 15, par = l >> 4;
    float bk = bvec[k];

    #pragma unroll
    for (int r = 0; r < 4; r++)
        ((float4*)xs[w][r])[l] = ((const float4*)x)[(node0 + r) * 32 + l];
    __syncwarp();

    float a0 = 0.f, a1 = 0.f, a2 = 0.f, a3 = 0.f;
    #pragma unroll
    for (int i = 0; i < 16; i++) {
        int ch = 2 * i + par;
        float4 wv = *(const float4*)&sWT[k][ch * 4];
        float4 x0 = ((const float4*)xs[w][0])[ch];
        float4 x1 = ((const float4*)xs[w][1])[ch];
        float4 x2 = ((const float4*)xs[w][2])[ch];
        float4 x3 = ((const float4*)xs[w][3])[ch];
        a0 = fmaf(x0.x, wv.x, a0); a0 = fmaf(x0.y, wv.y, a0);
        a0 = fmaf(x0.z, wv.z, a0); a0 = fmaf(x0.w, wv.w, a0);
        a1 = fmaf(x1.x, wv.x, a1); a1 = fmaf(x1.y, wv.y, a1);
        a1 = fmaf(x1.z, wv.z, a1); a1 = fmaf(x1.w, wv.w, a1);
        a2 = fmaf(x2.x, wv.x, a2); a2 = fmaf(x2.y, wv.y, a2);
        a2 = fmaf(x2.z, wv.z, a2); a2 = fmaf(x2.w, wv.w, a2);
        a3 = fmaf(x3.x, wv.x, a3); a3 = fmaf(x3.y, wv.y, a3);
        a3 = fmaf(x3.z, wv.z, a3); a3 = fmaf(x3.w, wv.w, a3);
    }
    float acc[4] = {a0, a1, a2, a3};
    #pragma unroll
    for (int r = 0; r < 4; r++) {
        float v = acc[r];
        v += __shfl_xor_sync(0xffffffffu, v, 16);
        v += bk;
        float e = __expf(v);
        float s1 = __fdividef(e, grp16_sum(e));
        e = __expf(s1);
        float s2 = __fdividef(e, grp16_sum(e));
        if (l < 16) {
            g_s [(node0 + r) * K_CL + l] = s2;
            g_sh[(node0 + r) * K_CL + l] = __float2half_rn(s2);
        }
    }
}

// ---------------- K2: pure edge scatter + mincut den ----------------------
__global__ void __launch_bounds__(256) k_edge(const float* __restrict__ ew,
                                              const int* __restrict__ esrc,
                                              const int* __restrict__ edst) {
    __shared__ float dsh[8];
    int t = threadIdx.x;
    int i = blockIdx.x * 256 + t;
    int2 s2 = ((const int2*)esrc)[i];
    int2 d2 = ((const int2*)edst)[i];
    float2 w2 = ((const float2*)ew)[i];

    const uint4* p0 = (const uint4*)(g_sh + d2.x * K_CL);
    const uint4* p1 = (const uint4*)(g_sh + d2.y * K_CL);
    uint4 a0 = p0[0], b0 = p0[1];
    uint4 a1 = p1[0], b1 = p1[1];

    float den = w2.x * ssq16(a0, b0) + w2.y * ssq16(a1, b1);

    __half2 wx = __float2half2_rn(w2.x);
    __half2 wy = __float2half2_rn(w2.y);

    __half* mp0 = g_Mh + s2.x * K_CL;
    __half* mp1 = g_Mh + s2.y * K_CL;
    red4h(mp0,     h2m(a0.x, wx), h2m(a0.y, wx), h2m(a0.z, wx), h2m(a0.w, wx));
    red4h(mp0 + 8, h2m(b0.x, wx), h2m(b0.y, wx), h2m(b0.z, wx), h2m(b0.w, wx));
    red4h(mp1,     h2m(a1.x, wy), h2m(a1.y, wy), h2m(a1.z, wy), h2m(a1.w, wy));
    red4h(mp1 + 8, h2m(b1.x, wy), h2m(b1.y, wy), h2m(b1.z, wy), h2m(b1.w, wy));

    #pragma unroll
    for (int d = 16; d > 0; d >>= 1) den += __shfl_xor_sync(0xffffffffu, den, d);
    if ((t & 31) == 0) dsh[t >> 5] = den;
    __syncthreads();
    if (t == 0) {
        float v = 0.f;
        #pragma unroll
        for (int q = 0; q < 8; q++) v += dsh[q];
        red1(&g_den, v);
    }
}

// ---------------- K3: [0,1024) adj+CC(+finalize), [1024,1088) OX+SELU -----
__global__ void __launch_bounds__(256) k_adj_ox(const float* __restrict__ x,
                                                float* __restrict__ out) {
    __shared__ float s_sh[CHUNK_A][K_CL];
    __shared__ float M_sh[CHUNK_A][K_CL];
    __shared__ float sx_sh[32][K_CL];
    __shared__ float sh8[8];
    __shared__ float dpool[K_CL];
    __shared__ int win;
    int t = threadIdx.x;

    if (blockIdx.x >= ADJ_BLOCKS) {
        // ======== OX branch: out_x[b] = selu(S_b^T X_b), one block per graph ====
        int b = blockIdx.x - ADJ_BLOCKS;
        int base = b * NODES_PER_G;
        int f = t & 127, half = t >> 7;
        float accx[8] = {0.f,0.f,0.f,0.f,0.f,0.f,0.f,0.f};

        for (int c = 0; c < NODES_PER_G / 32; c++) {   // 50 chunks of 32 nodes
            __syncthreads();
            if (t < 128) {
                int node = t >> 2, p = t & 3;
                ((float4*)sx_sh[node])[p] = ((const float4*)g_s)[(base + c * 32 + node) * 4 + p];
            }
            __syncthreads();
            #pragma unroll 8
            for (int n = 0; n < 32; n++) {
                float xv = __ldg(x + (base + c * 32 + n) * F_DIM + f);
                const float4* s4 = (const float4*)sx_sh[n];
                float4 sa = s4[half * 2], sb = s4[half * 2 + 1];
                accx[0] = fmaf(sa.x, xv, accx[0]);
                accx[1] = fmaf(sa.y, xv, accx[1]);
                accx[2] = fmaf(sa.z, xv, accx[2]);
                accx[3] = fmaf(sa.w, xv, accx[3]);
                accx[4] = fmaf(sb.x, xv, accx[4]);
                accx[5] = fmaf(sb.y, xv, accx[5]);
                accx[6] = fmaf(sb.z, xv, accx[6]);
                accx[7] = fmaf(sb.w, xv, accx[7]);
            }
        }
        #pragma unroll
        for (int kk = 0; kk < 8; kk++) {
            int kcol = half * 8 + kk;
            out[(b * K_CL + kcol) * F_DIM + f] = selu_f(accx[kk]);
        }
        return;
    }

    // ======== ADJ branch: S^T M + S^T S partials ========
    int b = blockIdx.x >> 4;
    int part = blockIdx.x & 15;
    int base = b * NODES_PER_G + part * NPART_A;
    int k1 = t >> 4, k2 = t & 15;

    float acc_adj = 0.f, acc_cc = 0.f;

    for (int c = 0; c < NPART_A / CHUNK_A; c++) {
        __syncthreads();
        if (t < 80) {
            int node = t >> 2, p = t & 3;
            int gi = base + c * CHUNK_A + node;
            ((float4*)s_sh[node])[p] = ((const float4*)g_s)[gi * 4 + p];
        } else if (t < 120) {
            int q = t - 80;
            int node = q >> 1, p = q & 1;
            int gi = base + c * CHUNK_A + node;
            uint4 h = ((const uint4*)g_Mh)[gi * 2 + p];
            float2 f0 = __half22float2(*(__half2*)&h.x);
            float2 f1 = __half22float2(*(__half2*)&h.y);
            float2 f2 = __half22float2(*(__half2*)&h.z);
            float2 f3 = __half22float2(*(__half2*)&h.w);
            float* mp = &M_sh[node][p * 8];
            mp[0] = f0.x; mp[1] = f0.y; mp[2] = f1.x; mp[3] = f1.y;
            mp[4] = f2.x; mp[5] = f2.y; mp[6] = f3.x; mp[7] = f3.y;
        }
        __syncthreads();
        #pragma unroll
        for (int n = 0; n < CHUNK_A; n++) {
            float sk1 = s_sh[n][k1];
            acc_adj = fmaf(sk1, M_sh[n][k2], acc_adj);
            acc_cc  = fmaf(sk1, s_sh[n][k2], acc_cc);
        }
    }
    red1(&g_adj[b * 256 + t], acc_adj);
    red1(&g_cc [b * 256 + t], acc_cc);

    // per-graph finalize by the last-arriving block
    __threadfence();
    __syncthreads();
    if (t == 0) {
        unsigned int old = atomicAdd(&g_cnt_adj[b], 1u);
        win = (old == SPLIT_A - 1);
    }
    __syncthreads();
    if (!win) return;
    __threadfence();

    float adj = __ldcg(&g_adj[b * 256 + t]);
    float cc  = __ldcg(&g_cc [b * 256 + t]);

    float tr = blockSum256s((k1 == k2) ? adj : 0.f, sh8);
    if (t == 0) red1(&g_num, tr);

    float nrm2 = blockSum256s(cc * cc, sh8);
    float nrm = sqrtf(nrm2);
    float diff = cc / nrm - ((k1 == k2) ? 0.25f : 0.f);
    float dsum = blockSum256s(diff * diff, sh8);
    if (t == 0) red1(&g_ortho, sqrtf(dsum));

    float am = (k1 == k2) ? 0.f : adj;
    float rs = grp16_sum(am);
    float dp = sqrtf(rs) + 1e-12f;
    if (k2 == 0) dpool[k1] = dp;
    __syncthreads();
    out[B_GRAPHS * K_CL * F_DIM + b * 256 + t] = am / (dp * dpool[k2]);

    // global scalars by the last-finishing graph
    __threadfence();
    __syncthreads();
    if (t == 0) {
        unsigned int old = atomicAdd(&g_cnt, 1u);
        if (old == B_GRAPHS - 1) {
            __threadfence();
            int off = B_GRAPHS * K_CL * F_DIM + B_GRAPHS * K_CL * K_CL;
            float num = __ldcg(&g_num);
            float den = __ldcg(&g_den);
            float ort = __ldcg(&g_ortho);
            out[off + 0] = -num / den;
            out[off + 1] = ort * (1.0f / (float)B_GRAPHS);
        }
    }
}

// ---------------- launch ----------------
extern "C" void kernel_launch(void* const* d_in, const int* in_sizes, int n_in,
                              void* d_out, int out_size) {
    const float* x    = (const float*)d_in[0];
    const float* W    = (const float*)d_in[1];
    const float* bv   = (const float*)d_in[2];
    const float* ew   = (const float*)d_in[3];
    const int*   esrc = (const int*)d_in[4];
    const int*   edst = (const int*)d_in[5];
    float* out = (float*)d_out;

    k_s     <<<N_NODES / 32, 256>>>(x, W, bv);               // 1
    k_edge  <<<EDGE_BLOCKS, 256>>>(ew, esrc, edst);          // 2
    k_adj_ox<<<ADJ_BLOCKS + OX_BLOCKS, 256>>>(x, out);       // 3
}

// round 12
// speedup vs baseline: 2.3817x; 2.3817x over previous
#include <cuda_runtime.h>
#include <cuda_fp16.h>
#include <cstdint>

#define B_GRAPHS 64
#define NODES_PER_G 1600
#define N_NODES (B_GRAPHS * NODES_PER_G)   // 102400
#define F_DIM 128
#define K_CL 16
#define E_EDGES (N_NODES * 32)             // 3276800
#define SPLIT_A 16
#define NPART_A (NODES_PER_G / SPLIT_A)    // 100
#define CHUNK_A 20
#define SPLIT_X 8
#define NPART_X (NODES_PER_G / SPLIT_X)    // 200
#define EDGE_BLOCKS (E_EDGES / 512)        // 6400
#define ADJ_BLOCKS (B_GRAPHS * SPLIT_A)    // 1024
#define OX_BLOCKS (B_GRAPHS * SPLIT_X)     // 512

// ---------------- device scratch ----------------
__device__ __align__(16) float g_s[N_NODES * K_CL];      // fp32 s (6.55 MB)
__device__ __align__(32) __half g_sh[N_NODES * K_CL];    // fp16 s copy (3.28 MB)
__device__ __align__(32) __half g_Mh[N_NODES * K_CL];    // fp16 M accumulator (3.28 MB)
__device__ float g_adj[B_GRAPHS * K_CL * K_CL];
__device__ float g_cc[B_GRAPHS * K_CL * K_CL];
__device__ __align__(16) float g_ox[B_GRAPHS * K_CL * F_DIM];
__device__ float g_num;
__device__ float g_den;
__device__ float g_ortho;
__device__ unsigned int g_cnt;
__device__ unsigned int g_cnt_adj[B_GRAPHS];
__device__ unsigned int g_cnt_ox[B_GRAPHS];

// ---------------- helpers ----------------
__device__ __forceinline__ void red1(float* p, float a) {
    asm volatile("red.global.add.f32 [%0], %1;" :: "l"(p), "f"(a) : "memory");
}
__device__ __forceinline__ void red4h(__half* p, uint32_t r0, uint32_t r1,
                                      uint32_t r2, uint32_t r3) {
    asm volatile("red.global.add.noftz.v4.f16x2 [%0], {%1,%2,%3,%4};"
                 :: "l"(p), "r"(r0), "r"(r1), "r"(r2), "r"(r3) : "memory");
}
__device__ __forceinline__ __half2 u2h(uint32_t v) { return *(__half2*)&v; }
__device__ __forceinline__ uint32_t h2m(uint32_t v, __half2 w) {
    __half2 h = __hmul2(u2h(v), w);
    return *(uint32_t*)&h;
}
__device__ __forceinline__ float ssq16(uint4 a, uint4 b) {
    __half2 q = __hmul2(u2h(a.x), u2h(a.x));
    q = __hfma2(u2h(a.y), u2h(a.y), q);
    q = __hfma2(u2h(a.z), u2h(a.z), q);
    q = __hfma2(u2h(a.w), u2h(a.w), q);
    q = __hfma2(u2h(b.x), u2h(b.x), q);
    q = __hfma2(u2h(b.y), u2h(b.y), q);
    q = __hfma2(u2h(b.z), u2h(b.z), q);
    q = __hfma2(u2h(b.w), u2h(b.w), q);
    float2 f = __half22float2(q);
    return f.x + f.y;
}

__device__ __forceinline__ float selu_f(float v) {
    const float scale = 1.0507009873554805f;
    const float alpha = 1.6732632423543772f;
    return v > 0.f ? scale * v : scale * alpha * (__expf(v) - 1.f);
}

__device__ __forceinline__ float grp16_sum(float v) {
    v += __shfl_xor_sync(0xffffffffu, v, 1);
    v += __shfl_xor_sync(0xffffffffu, v, 2);
    v += __shfl_xor_sync(0xffffffffu, v, 4);
    v += __shfl_xor_sync(0xffffffffu, v, 8);
    return v;
}

__device__ __forceinline__ float blockSum256s(float v, volatile float* sh8) {
    int t = threadIdx.x;
    #pragma unroll
    for (int d = 16; d > 0; d >>= 1) v += __shfl_xor_sync(0xffffffffu, v, d);
    if ((t & 31) == 0) sh8[t >> 5] = v;
    __syncthreads();
    float r = sh8[0] + sh8[1] + sh8[2] + sh8[3] + sh8[4] + sh8[5] + sh8[6] + sh8[7];
    __syncthreads();
    return r;
}

// ---------------- K1: s = softmax^2(xW+b), 4 nodes/warp + zeroing ---------
__global__ void __launch_bounds__(256) k_s(const float* __restrict__ x,
                                           const float* __restrict__ W,
                                           const float* __restrict__ bvec) {
    __shared__ float sWT[K_CL][132];
    __shared__ float xs[8][4][F_DIM];
    int t = threadIdx.x;
    int bid = blockIdx.x;                 // grid = 3200

    if (t < 64) ((uint4*)g_Mh)[bid * 64 + t] = make_uint4(0u,0u,0u,0u);
    if (bid < 128) ((float4*)g_ox)[bid * 256 + t] = make_float4(0.f,0.f,0.f,0.f);
    if (bid < 16) {
        int i = bid * 256 + t;
        ((float4*)g_adj)[i] = make_float4(0.f,0.f,0.f,0.f);
        ((float4*)g_cc)[i]  = make_float4(0.f,0.f,0.f,0.f);
    }
    if (bid == 0) {
        if (t < B_GRAPHS) { g_cnt_adj[t] = 0u; g_cnt_ox[t] = 0u; }
        if (t == 0) { g_num = 0.f; g_den = 0.f; g_ortho = 0.f; g_cnt = 0u; }
    }

    for (int i = t; i < F_DIM * K_CL; i += 256) {
        int j = i >> 4, k = i & 15;
        sWT[k][j] = W[i];
    }
    __syncthreads();

    int w = t >> 5, l = t & 31;
    int node0 = bid * 32 + w * 4;
    int k = l & 15, par = l >> 4;
    float bk = bvec[k];

    #pragma unroll
    for (int r = 0; r < 4; r++)
        ((float4*)xs[w][r])[l] = ((const float4*)x)[(node0 + r) * 32 + l];
    __syncwarp();

    float a0 = 0.f, a1 = 0.f, a2 = 0.f, a3 = 0.f;
    #pragma unroll
    for (int i = 0; i < 16; i++) {
        int ch = 2 * i + par;
        float4 wv = *(const float4*)&sWT[k][ch * 4];
        float4 x0 = ((const float4*)xs[w][0])[ch];
        float4 x1 = ((const float4*)xs[w][1])[ch];
        float4 x2 = ((const float4*)xs[w][2])[ch];
        float4 x3 = ((const float4*)xs[w][3])[ch];
        a0 = fmaf(x0.x, wv.x, a0); a0 = fmaf(x0.y, wv.y, a0);
        a0 = fmaf(x0.z, wv.z, a0); a0 = fmaf(x0.w, wv.w, a0);
        a1 = fmaf(x1.x, wv.x, a1); a1 = fmaf(x1.y, wv.y, a1);
        a1 = fmaf(x1.z, wv.z, a1); a1 = fmaf(x1.w, wv.w, a1);
        a2 = fmaf(x2.x, wv.x, a2); a2 = fmaf(x2.y, wv.y, a2);
        a2 = fmaf(x2.z, wv.z, a2); a2 = fmaf(x2.w, wv.w, a2);
        a3 = fmaf(x3.x, wv.x, a3); a3 = fmaf(x3.y, wv.y, a3);
        a3 = fmaf(x3.z, wv.z, a3); a3 = fmaf(x3.w, wv.w, a3);
    }
    float acc[4] = {a0, a1, a2, a3};
    #pragma unroll
    for (int r = 0; r < 4; r++) {
        float v = acc[r];
        v += __shfl_xor_sync(0xffffffffu, v, 16);
        v += bk;
        float e = __expf(v);
        float s1 = __fdividef(e, grp16_sum(e));
        e = __expf(s1);
        float s2 = __fdividef(e, grp16_sum(e));
        if (l < 16) {
            g_s [(node0 + r) * K_CL + l] = s2;
            g_sh[(node0 + r) * K_CL + l] = __float2half_rn(s2);
        }
    }
}

// ---------------- K2: pure edge scatter + mincut den ----------------------
__global__ void __launch_bounds__(256) k_edge(const float* __restrict__ ew,
                                              const int* __restrict__ esrc,
                                              const int* __restrict__ edst) {
    __shared__ float dsh[8];
    int t = threadIdx.x;
    int i = blockIdx.x * 256 + t;
    int2 s2 = ((const int2*)esrc)[i];
    int2 d2 = ((const int2*)edst)[i];
    float2 w2 = ((const float2*)ew)[i];

    const uint4* p0 = (const uint4*)(g_sh + d2.x * K_CL);
    const uint4* p1 = (const uint4*)(g_sh + d2.y * K_CL);
    uint4 a0 = p0[0], b0 = p0[1];
    uint4 a1 = p1[0], b1 = p1[1];

    float den = w2.x * ssq16(a0, b0) + w2.y * ssq16(a1, b1);

    __half2 wx = __float2half2_rn(w2.x);
    __half2 wy = __float2half2_rn(w2.y);

    __half* mp0 = g_Mh + s2.x * K_CL;
    __half* mp1 = g_Mh + s2.y * K_CL;
    red4h(mp0,     h2m(a0.x, wx), h2m(a0.y, wx), h2m(a0.z, wx), h2m(a0.w, wx));
    red4h(mp0 + 8, h2m(b0.x, wx), h2m(b0.y, wx), h2m(b0.z, wx), h2m(b0.w, wx));
    red4h(mp1,     h2m(a1.x, wy), h2m(a1.y, wy), h2m(a1.z, wy), h2m(a1.w, wy));
    red4h(mp1 + 8, h2m(b1.x, wy), h2m(b1.y, wy), h2m(b1.z, wy), h2m(b1.w, wy));

    #pragma unroll
    for (int d = 16; d > 0; d >>= 1) den += __shfl_xor_sync(0xffffffffu, den, d);
    if ((t & 31) == 0) dsh[t >> 5] = den;
    __syncthreads();
    if (t == 0) {
        float v = 0.f;
        #pragma unroll
        for (int q = 0; q < 8; q++) v += dsh[q];
        red1(&g_den, v);
    }
}

// ---------------- K3: [0,1024) adj+CC(+finalize), [1024,1536) OX(+SELU) ---
__global__ void __launch_bounds__(256) k_adj_ox(const float* __restrict__ x,
                                                float* __restrict__ out) {
    __shared__ float s_sh[CHUNK_A][K_CL];
    __shared__ float M_sh[CHUNK_A][K_CL];
    __shared__ float sh8[8];
    __shared__ float dpool[K_CL];
    __shared__ int win;
    int t = threadIdx.x;

    if (blockIdx.x >= ADJ_BLOCKS) {
        // ======== OX branch: 8 blocks per graph, 200 nodes each ========
        int bo = blockIdx.x - ADJ_BLOCKS;
        int b = bo >> 3;
        int part = bo & 7;
        int base = b * NODES_PER_G + part * NPART_X;
        int f = t & 127, half = t >> 7;
        float accx[8] = {0.f,0.f,0.f,0.f,0.f,0.f,0.f,0.f};

        for (int c = 0; c < NPART_X / 8; c++) {   // 25 chunks of 8 nodes
            __syncthreads();
            if (t < 32) {
                int node = t >> 2, p = t & 3;
                ((float4*)s_sh[node])[p] = ((const float4*)g_s)[(base + c * 8 + node) * 4 + p];
            }
            __syncthreads();
            #pragma unroll
            for (int n = 0; n < 8; n++) {
                float xv = __ldg(x + (base + c * 8 + n) * F_DIM + f);
                const float4* s4 = (const float4*)s_sh[n];
                float4 sa = s4[half * 2], sb = s4[half * 2 + 1];
                accx[0] = fmaf(sa.x, xv, accx[0]);
                accx[1] = fmaf(sa.y, xv, accx[1]);
                accx[2] = fmaf(sa.z, xv, accx[2]);
                accx[3] = fmaf(sa.w, xv, accx[3]);
                accx[4] = fmaf(sb.x, xv, accx[4]);
                accx[5] = fmaf(sb.y, xv, accx[5]);
                accx[6] = fmaf(sb.z, xv, accx[6]);
                accx[7] = fmaf(sb.w, xv, accx[7]);
            }
        }
        #pragma unroll
        for (int kk = 0; kk < 8; kk++) {
            int kcol = half * 8 + kk;
            red1(&g_ox[(b * K_CL + kcol) * F_DIM + f], accx[kk]);
        }
        // last of the 8 OX blocks applies SELU for this graph
        __threadfence();
        __syncthreads();
        if (t == 0) {
            unsigned int old = atomicAdd(&g_cnt_ox[b], 1u);
            win = (old == SPLIT_X - 1);
        }
        __syncthreads();
        if (!win) return;
        __threadfence();
        #pragma unroll
        for (int q = 0; q < 8; q++) {
            int i = b * 2048 + q * 256 + t;
            out[i] = selu_f(__ldcg(&g_ox[i]));
        }
        return;
    }

    // ======== ADJ branch: S^T M + S^T S partials ========
    int b = blockIdx.x >> 4;
    int part = blockIdx.x & 15;
    int base = b * NODES_PER_G + part * NPART_A;
    int k1 = t >> 4, k2 = t & 15;

    float acc_adj = 0.f, acc_cc = 0.f;

    for (int c = 0; c < NPART_A / CHUNK_A; c++) {
        __syncthreads();
        if (t < 80) {
            int node = t >> 2, p = t & 3;
            int gi = base + c * CHUNK_A + node;
            ((float4*)s_sh[node])[p] = ((const float4*)g_s)[gi * 4 + p];
        } else if (t < 120) {
            int q = t - 80;
            int node = q >> 1, p = q & 1;
            int gi = base + c * CHUNK_A + node;
            uint4 h = ((const uint4*)g_Mh)[gi * 2 + p];
            float2 f0 = __half22float2(*(__half2*)&h.x);
            float2 f1 = __half22float2(*(__half2*)&h.y);
            float2 f2 = __half22float2(*(__half2*)&h.z);
            float2 f3 = __half22float2(*(__half2*)&h.w);
            float* mp = &M_sh[node][p * 8];
            mp[0] = f0.x; mp[1] = f0.y; mp[2] = f1.x; mp[3] = f1.y;
            mp[4] = f2.x; mp[5] = f2.y; mp[6] = f3.x; mp[7] = f3.y;
        }
        __syncthreads();
        #pragma unroll
        for (int n = 0; n < CHUNK_A; n++) {
            float sk1 = s_sh[n][k1];
            acc_adj = fmaf(sk1, M_sh[n][k2], acc_adj);
            acc_cc  = fmaf(sk1, s_sh[n][k2], acc_cc);
        }
    }
    red1(&g_adj[b * 256 + t], acc_adj);
    red1(&g_cc [b * 256 + t], acc_cc);

    // per-graph finalize by the last-arriving block
    __threadfence();
    __syncthreads();
    if (t == 0) {
        unsigned int old = atomicAdd(&g_cnt_adj[b], 1u);
        win = (old == SPLIT_A - 1);
    }
    __syncthreads();
    if (!win) return;
    __threadfence();

    float adj = __ldcg(&g_adj[b * 256 + t]);
    float cc  = __ldcg(&g_cc [b * 256 + t]);

    float tr = blockSum256s((k1 == k2) ? adj : 0.f, sh8);
    if (t == 0) red1(&g_num, tr);

    float nrm2 = blockSum256s(cc * cc, sh8);
    float nrm = sqrtf(nrm2);
    float diff = cc / nrm - ((k1 == k2) ? 0.25f : 0.f);
    float dsum = blockSum256s(diff * diff, sh8);
    if (t == 0) red1(&g_ortho, sqrtf(dsum));

    float am = (k1 == k2) ? 0.f : adj;
    float rs = grp16_sum(am);
    float dp = sqrtf(rs) + 1e-12f;
    if (k2 == 0) dpool[k1] = dp;
    __syncthreads();
    out[B_GRAPHS * K_CL * F_DIM + b * 256 + t] = am / (dp * dpool[k2]);

    // global scalars by the last-finishing graph
    __threadfence();
    __syncthreads();
    if (t == 0) {
        unsigned int old = atomicAdd(&g_cnt, 1u);
        if (old == B_GRAPHS - 1) {
            __threadfence();
            int off = B_GRAPHS * K_CL * F_DIM + B_GRAPHS * K_CL * K_CL;
            float num = __ldcg(&g_num);
            float den = __ldcg(&g_den);
            float ort = __ldcg(&g_ortho);
            out[off + 0] = -num / den;
            out[off + 1] = ort * (1.0f / (float)B_GRAPHS);
        }
    }
}

// ---------------- launch ----------------
extern "C" void kernel_launch(void* const* d_in, const int* in_sizes, int n_in,
                              void* d_out, int out_size) {
    const float* x    = (const float*)d_in[0];
    const float* W    = (const float*)d_in[1];
    const float* bv   = (const float*)d_in[2];
    const float* ew   = (const float*)d_in[3];
    const int*   esrc = (const int*)d_in[4];
    const int*   edst = (const int*)d_in[5];
    float* out = (float*)d_out;

    k_s     <<<N_NODES / 32, 256>>>(x, W, bv);               // 1
    k_edge  <<<EDGE_BLOCKS, 256>>>(ew, esrc, edst);          // 2
    k_adj_ox<<<ADJ_BLOCKS + OX_BLOCKS, 256>>>(x, out);       // 3
}

// round 13
// speedup vs baseline: 2.5097x; 1.0537x over previous
#include <cuda_runtime.h>
#include <cuda_fp16.h>
#include <cstdint>

#define B_GRAPHS 64
#define NODES_PER_G 1600
#define N_NODES (B_GRAPHS * NODES_PER_G)   // 102400
#define F_DIM 128
#define K_CL 16
#define E_EDGES (N_NODES * 32)             // 3276800
#define SPLIT_A 16
#define NPART_A (NODES_PER_G / SPLIT_A)    // 100
#define CHUNK_A 20
#define SPLIT_X 8
#define NPART_X (NODES_PER_G / SPLIT_X)    // 200
#define CHUNK_X 40
#define EDGE_BLOCKS (E_EDGES / 512)        // 6400
#define ADJ_BLOCKS (B_GRAPHS * SPLIT_A)    // 1024
#define OX_BLOCKS (B_GRAPHS * SPLIT_X)     // 512

// ---------------- device scratch ----------------
__device__ __align__(16) float g_s[N_NODES * K_CL];      // fp32 s (6.55 MB)
__device__ __align__(32) __half g_sh[N_NODES * K_CL];    // fp16 s copy (3.28 MB)
__device__ __align__(32) __half g_Mh[N_NODES * K_CL];    // fp16 M accumulator (3.28 MB)
__device__ float g_adj[B_GRAPHS * K_CL * K_CL];
__device__ float g_cc[B_GRAPHS * K_CL * K_CL];
__device__ __align__(16) float g_ox[B_GRAPHS * K_CL * F_DIM];
__device__ float g_num;
__device__ float g_den;
__device__ float g_ortho;
__device__ unsigned int g_cnt;
__device__ unsigned int g_cnt_adj[B_GRAPHS];
__device__ unsigned int g_cnt_ox[B_GRAPHS];

// ---------------- helpers ----------------
__device__ __forceinline__ void red1(float* p, float a) {
    asm volatile("red.global.add.f32 [%0], %1;" :: "l"(p), "f"(a) : "memory");
}
__device__ __forceinline__ void red4h(__half* p, uint32_t r0, uint32_t r1,
                                      uint32_t r2, uint32_t r3) {
    asm volatile("red.global.add.noftz.v4.f16x2 [%0], {%1,%2,%3,%4};"
                 :: "l"(p), "r"(r0), "r"(r1), "r"(r2), "r"(r3) : "memory");
}
__device__ __forceinline__ __half2 u2h(uint32_t v) { return *(__half2*)&v; }
__device__ __forceinline__ uint32_t h2m(uint32_t v, __half2 w) {
    __half2 h = __hmul2(u2h(v), w);
    return *(uint32_t*)&h;
}
__device__ __forceinline__ float ssq16(uint4 a, uint4 b) {
    __half2 q = __hmul2(u2h(a.x), u2h(a.x));
    q = __hfma2(u2h(a.y), u2h(a.y), q);
    q = __hfma2(u2h(a.z), u2h(a.z), q);
    q = __hfma2(u2h(a.w), u2h(a.w), q);
    q = __hfma2(u2h(b.x), u2h(b.x), q);
    q = __hfma2(u2h(b.y), u2h(b.y), q);
    q = __hfma2(u2h(b.z), u2h(b.z), q);
    q = __hfma2(u2h(b.w), u2h(b.w), q);
    float2 f = __half22float2(q);
    return f.x + f.y;
}

__device__ __forceinline__ float selu_f(float v) {
    const float scale = 1.0507009873554805f;
    const float alpha = 1.6732632423543772f;
    return v > 0.f ? scale * v : scale * alpha * (__expf(v) - 1.f);
}

__device__ __forceinline__ float grp16_sum(float v) {
    v += __shfl_xor_sync(0xffffffffu, v, 1);
    v += __shfl_xor_sync(0xffffffffu, v, 2);
    v += __shfl_xor_sync(0xffffffffu, v, 4);
    v += __shfl_xor_sync(0xffffffffu, v, 8);
    return v;
}

__device__ __forceinline__ float blockSum256s(float v, volatile float* sh8) {
    int t = threadIdx.x;
    #pragma unroll
    for (int d = 16; d > 0; d >>= 1) v += __shfl_xor_sync(0xffffffffu, v, d);
    if ((t & 31) == 0) sh8[t >> 5] = v;
    __syncthreads();
    float r = sh8[0] + sh8[1] + sh8[2] + sh8[3] + sh8[4] + sh8[5] + sh8[6] + sh8[7];
    __syncthreads();
    return r;
}

// ---------------- K1: s = softmax^2(xW+b), 4 nodes/warp + zeroing ---------
__global__ void __launch_bounds__(256) k_s(const float* __restrict__ x,
                                           const float* __restrict__ W,
                                           const float* __restrict__ bvec) {
    __shared__ float sWT[K_CL][132];
    __shared__ float xs[8][4][F_DIM];
    int t = threadIdx.x;
    int bid = blockIdx.x;                 // grid = 3200

    if (t < 64) ((uint4*)g_Mh)[bid * 64 + t] = make_uint4(0u,0u,0u,0u);
    if (bid < 128) ((float4*)g_ox)[bid * 256 + t] = make_float4(0.f,0.f,0.f,0.f);
    if (bid < 16) {
        int i = bid * 256 + t;
        ((float4*)g_adj)[i] = make_float4(0.f,0.f,0.f,0.f);
        ((float4*)g_cc)[i]  = make_float4(0.f,0.f,0.f,0.f);
    }
    if (bid == 0) {
        if (t < B_GRAPHS) { g_cnt_adj[t] = 0u; g_cnt_ox[t] = 0u; }
        if (t == 0) { g_num = 0.f; g_den = 0.f; g_ortho = 0.f; g_cnt = 0u; }
    }

    for (int i = t; i < F_DIM * K_CL; i += 256) {
        int j = i >> 4, k = i & 15;
        sWT[k][j] = W[i];
    }
    __syncthreads();

    int w = t >> 5, l = t & 31;
    int node0 = bid * 32 + w * 4;
    int k = l & 15, par = l >> 4;
    float bk = bvec[k];

    #pragma unroll
    for (int r = 0; r < 4; r++)
        ((float4*)xs[w][r])[l] = ((const float4*)x)[(node0 + r) * 32 + l];
    __syncwarp();

    float a0 = 0.f, a1 = 0.f, a2 = 0.f, a3 = 0.f;
    #pragma unroll
    for (int i = 0; i < 16; i++) {
        int ch = 2 * i + par;
        float4 wv = *(const float4*)&sWT[k][ch * 4];
        float4 x0 = ((const float4*)xs[w][0])[ch];
        float4 x1 = ((const float4*)xs[w][1])[ch];
        float4 x2 = ((const float4*)xs[w][2])[ch];
        float4 x3 = ((const float4*)xs[w][3])[ch];
        a0 = fmaf(x0.x, wv.x, a0); a0 = fmaf(x0.y, wv.y, a0);
        a0 = fmaf(x0.z, wv.z, a0); a0 = fmaf(x0.w, wv.w, a0);
        a1 = fmaf(x1.x, wv.x, a1); a1 = fmaf(x1.y, wv.y, a1);
        a1 = fmaf(x1.z, wv.z, a1); a1 = fmaf(x1.w, wv.w, a1);
        a2 = fmaf(x2.x, wv.x, a2); a2 = fmaf(x2.y, wv.y, a2);
        a2 = fmaf(x2.z, wv.z, a2); a2 = fmaf(x2.w, wv.w, a2);
        a3 = fmaf(x3.x, wv.x, a3); a3 = fmaf(x3.y, wv.y, a3);
        a3 = fmaf(x3.z, wv.z, a3); a3 = fmaf(x3.w, wv.w, a3);
    }
    float acc[4] = {a0, a1, a2, a3};
    #pragma unroll
    for (int r = 0; r < 4; r++) {
        float v = acc[r];
        v += __shfl_xor_sync(0xffffffffu, v, 16);
        v += bk;
        float e = __expf(v);
        float s1 = __fdividef(e, grp16_sum(e));
        e = __expf(s1);
        float s2 = __fdividef(e, grp16_sum(e));
        if (l < 16) {
            g_s [(node0 + r) * K_CL + l] = s2;
            g_sh[(node0 + r) * K_CL + l] = __float2half_rn(s2);
        }
    }
}

// ---------------- K2: pure edge scatter + mincut den ----------------------
__global__ void __launch_bounds__(256) k_edge(const float* __restrict__ ew,
                                              const int* __restrict__ esrc,
                                              const int* __restrict__ edst) {
    __shared__ float dsh[8];
    int t = threadIdx.x;
    int i = blockIdx.x * 256 + t;
    int2 s2 = ((const int2*)esrc)[i];
    int2 d2 = ((const int2*)edst)[i];
    float2 w2 = ((const float2*)ew)[i];

    const uint4* p0 = (const uint4*)(g_sh + d2.x * K_CL);
    const uint4* p1 = (const uint4*)(g_sh + d2.y * K_CL);
    uint4 a0 = p0[0], b0 = p0[1];
    uint4 a1 = p1[0], b1 = p1[1];

    float den = w2.x * ssq16(a0, b0) + w2.y * ssq16(a1, b1);

    __half2 wx = __float2half2_rn(w2.x);
    __half2 wy = __float2half2_rn(w2.y);

    __half* mp0 = g_Mh + s2.x * K_CL;
    __half* mp1 = g_Mh + s2.y * K_CL;
    red4h(mp0,     h2m(a0.x, wx), h2m(a0.y, wx), h2m(a0.z, wx), h2m(a0.w, wx));
    red4h(mp0 + 8, h2m(b0.x, wx), h2m(b0.y, wx), h2m(b0.z, wx), h2m(b0.w, wx));
    red4h(mp1,     h2m(a1.x, wy), h2m(a1.y, wy), h2m(a1.z, wy), h2m(a1.w, wy));
    red4h(mp1 + 8, h2m(b1.x, wy), h2m(b1.y, wy), h2m(b1.z, wy), h2m(b1.w, wy));

    #pragma unroll
    for (int d = 16; d > 0; d >>= 1) den += __shfl_xor_sync(0xffffffffu, den, d);
    if ((t & 31) == 0) dsh[t >> 5] = den;
    __syncthreads();
    if (t == 0) {
        float v = 0.f;
        #pragma unroll
        for (int q = 0; q < 8; q++) v += dsh[q];
        red1(&g_den, v);
    }
}

// ---------------- K3: [0,512) OX(+SELU), [512,1536) adj+CC(+finalize) -----
__global__ void __launch_bounds__(256) k_adj_ox(const float* __restrict__ x,
                                                float* __restrict__ out) {
    __shared__ float s_sh[CHUNK_A][K_CL];
    __shared__ float M_sh[CHUNK_A][K_CL];
    __shared__ float sx_sh[CHUNK_X][K_CL];
    __shared__ float sh8[8];
    __shared__ float dpool[K_CL];
    __shared__ int win;
    int t = threadIdx.x;

    if (blockIdx.x < OX_BLOCKS) {
        // ======== OX branch FIRST (long pole): 8 blocks/graph, 200 nodes ========
        int bo = blockIdx.x;
        int b = bo >> 3;
        int part = bo & 7;
        int base = b * NODES_PER_G + part * NPART_X;
        int f = t & 127, half = t >> 7;
        float accx[8] = {0.f,0.f,0.f,0.f,0.f,0.f,0.f,0.f};

        for (int c = 0; c < NPART_X / CHUNK_X; c++) {   // 5 chunks of 40 nodes
            __syncthreads();
            if (t < CHUNK_X * 4) {
                int node = t >> 2, p = t & 3;
                ((float4*)sx_sh[node])[p] = ((const float4*)g_s)[(base + c * CHUNK_X + node) * 4 + p];
            }
            __syncthreads();
            #pragma unroll 8
            for (int n = 0; n < CHUNK_X; n++) {
                float xv = __ldg(x + (base + c * CHUNK_X + n) * F_DIM + f);
                const float4* s4 = (const float4*)sx_sh[n];
                float4 sa = s4[half * 2], sb = s4[half * 2 + 1];
                accx[0] = fmaf(sa.x, xv, accx[0]);
                accx[1] = fmaf(sa.y, xv, accx[1]);
                accx[2] = fmaf(sa.z, xv, accx[2]);
                accx[3] = fmaf(sa.w, xv, accx[3]);
                accx[4] = fmaf(sb.x, xv, accx[4]);
                accx[5] = fmaf(sb.y, xv, accx[5]);
                accx[6] = fmaf(sb.z, xv, accx[6]);
                accx[7] = fmaf(sb.w, xv, accx[7]);
            }
        }
        #pragma unroll
        for (int kk = 0; kk < 8; kk++) {
            int kcol = half * 8 + kk;
            red1(&g_ox[(b * K_CL + kcol) * F_DIM + f], accx[kk]);
        }
        // last of the 8 OX blocks applies SELU for this graph
        __threadfence();
        __syncthreads();
        if (t == 0) {
            unsigned int old = atomicAdd(&g_cnt_ox[b], 1u);
            win = (old == SPLIT_X - 1);
        }
        __syncthreads();
        if (!win) return;
        __threadfence();
        #pragma unroll
        for (int q = 0; q < 8; q++) {
            int i = b * 2048 + q * 256 + t;
            out[i] = selu_f(__ldcg(&g_ox[i]));
        }
        return;
    }

    // ======== ADJ branch: S^T M + S^T S partials ========
    int bb = blockIdx.x - OX_BLOCKS;
    int b = bb >> 4;
    int part = bb & 15;
    int base = b * NODES_PER_G + part * NPART_A;
    int k1 = t >> 4, k2 = t & 15;

    float acc_adj = 0.f, acc_cc = 0.f;

    for (int c = 0; c < NPART_A / CHUNK_A; c++) {
        __syncthreads();
        if (t < 80) {
            int node = t >> 2, p = t & 3;
            int gi = base + c * CHUNK_A + node;
            ((float4*)s_sh[node])[p] = ((const float4*)g_s)[gi * 4 + p];
        } else if (t < 120) {
            int q = t - 80;
            int node = q >> 1, p = q & 1;
            int gi = base + c * CHUNK_A + node;
            uint4 h = ((const uint4*)g_Mh)[gi * 2 + p];
            float2 f0 = __half22float2(*(__half2*)&h.x);
            float2 f1 = __half22float2(*(__half2*)&h.y);
            float2 f2 = __half22float2(*(__half2*)&h.z);
            float2 f3 = __half22float2(*(__half2*)&h.w);
            float* mp = &M_sh[node][p * 8];
            mp[0] = f0.x; mp[1] = f0.y; mp[2] = f1.x; mp[3] = f1.y;
            mp[4] = f2.x; mp[5] = f2.y; mp[6] = f3.x; mp[7] = f3.y;
        }
        __syncthreads();
        #pragma unroll
        for (int n = 0; n < CHUNK_A; n++) {
            float sk1 = s_sh[n][k1];
            acc_adj = fmaf(sk1, M_sh[n][k2], acc_adj);
            acc_cc  = fmaf(sk1, s_sh[n][k2], acc_cc);
        }
    }
    red1(&g_adj[b * 256 + t], acc_adj);
    red1(&g_cc [b * 256 + t], acc_cc);

    // per-graph finalize by the last-arriving block
    __threadfence();
    __syncthreads();
    if (t == 0) {
        unsigned int old = atomicAdd(&g_cnt_adj[b], 1u);
        win = (old == SPLIT_A - 1);
    }
    __syncthreads();
    if (!win) return;
    __threadfence();

    float adj = __ldcg(&g_adj[b * 256 + t]);
    float cc  = __ldcg(&g_cc [b * 256 + t]);

    float tr = blockSum256s((k1 == k2) ? adj : 0.f, sh8);
    if (t == 0) red1(&g_num, tr);

    float nrm2 = blockSum256s(cc * cc, sh8);
    float nrm = sqrtf(nrm2);
    float diff = cc / nrm - ((k1 == k2) ? 0.25f : 0.f);
    float dsum = blockSum256s(diff * diff, sh8);
    if (t == 0) red1(&g_ortho, sqrtf(dsum));

    float am = (k1 == k2) ? 0.f : adj;
    float rs = grp16_sum(am);
    float dp = sqrtf(rs) + 1e-12f;
    if (k2 == 0) dpool[k1] = dp;
    __syncthreads();
    out[B_GRAPHS * K_CL * F_DIM + b * 256 + t] = am / (dp * dpool[k2]);

    // global scalars by the last-finishing graph
    __threadfence();
    __syncthreads();
    if (t == 0) {
        unsigned int old = atomicAdd(&g_cnt, 1u);
        if (old == B_GRAPHS - 1) {
            __threadfence();
            int off = B_GRAPHS * K_CL * F_DIM + B_GRAPHS * K_CL * K_CL;
            float num = __ldcg(&g_num);
            float den = __ldcg(&g_den);
            float ort = __ldcg(&g_ortho);
            out[off + 0] = -num / den;
            out[off + 1] = ort * (1.0f / (float)B_GRAPHS);
        }
    }
}

// ---------------- launch ----------------
extern "C" void kernel_launch(void* const* d_in, const int* in_sizes, int n_in,
                              void* d_out, int out_size) {
    const float* x    = (const float*)d_in[0];
    const float* W    = (const float*)d_in[1];
    const float* bv   = (const float*)d_in[2];
    const float* ew   = (const float*)d_in[3];
    const int*   esrc = (const int*)d_in[4];
    const int*   edst = (const int*)d_in[5];
    float* out = (float*)d_out;

    k_s     <<<N_NODES / 32, 256>>>(x, W, bv);               // 1
    k_edge  <<<EDGE_BLOCKS, 256>>>(ew, esrc, edst);          // 2
    k_adj_ox<<<OX_BLOCKS + ADJ_BLOCKS, 256>>>(x, out);       // 3
}

// round 14
// speedup vs baseline: 2.5385x; 1.0115x over previous
#include <cuda_runtime.h>
#include <cuda_fp16.h>
#include <cstdint>

#define B_GRAPHS 64
#define NODES_PER_G 1600
#define N_NODES (B_GRAPHS * NODES_PER_G)   // 102400
#define F_DIM 128
#define K_CL 16
#define E_EDGES (N_NODES * 32)             // 3276800
#define SPLIT_A 16
#define NPART_A (NODES_PER_G / SPLIT_A)    // 100
#define CHUNK_A 20
#define SPLIT_X 8
#define NPART_X (NODES_PER_G / SPLIT_X)    // 200
#define CHUNK_X 40
#define EDGE_BLOCKS (E_EDGES / 512)        // 6400
#define ADJ_BLOCKS (B_GRAPHS * SPLIT_A)    // 1024
#define OX_BLOCKS (B_GRAPHS * SPLIT_X)     // 512

// ---------------- device scratch ----------------
__device__ __align__(16) float g_s[N_NODES * K_CL];      // fp32 s (6.55 MB)
__device__ __align__(32) __half g_sh[N_NODES * K_CL];    // fp16 s copy (3.28 MB)
__device__ __align__(32) __half g_Mh[N_NODES * K_CL];    // fp16 M accumulator (3.28 MB)
__device__ float g_adj[B_GRAPHS * K_CL * K_CL];
__device__ float g_cc[B_GRAPHS * K_CL * K_CL];
__device__ __align__(16) float g_ox[B_GRAPHS * K_CL * F_DIM];
__device__ float g_num;
__device__ float g_den;
__device__ float g_ortho;
__device__ unsigned int g_cnt;
__device__ unsigned int g_cnt_adj[B_GRAPHS];
__device__ unsigned int g_cnt_ox[B_GRAPHS];

// ---------------- helpers ----------------
__device__ __forceinline__ void red1(float* p, float a) {
    asm volatile("red.global.add.f32 [%0], %1;" :: "l"(p), "f"(a) : "memory");
}
__device__ __forceinline__ void red4h(__half* p, uint32_t r0, uint32_t r1,
                                      uint32_t r2, uint32_t r3) {
    asm volatile("red.global.add.noftz.v4.f16x2 [%0], {%1,%2,%3,%4};"
                 :: "l"(p), "r"(r0), "r"(r1), "r"(r2), "r"(r3) : "memory");
}
__device__ __forceinline__ __half2 u2h(uint32_t v) { return *(__half2*)&v; }
__device__ __forceinline__ uint32_t h2m(uint32_t v, __half2 w) {
    __half2 h = __hmul2(u2h(v), w);
    return *(uint32_t*)&h;
}
__device__ __forceinline__ float ssq16(uint4 a, uint4 b) {
    __half2 q = __hmul2(u2h(a.x), u2h(a.x));
    q = __hfma2(u2h(a.y), u2h(a.y), q);
    q = __hfma2(u2h(a.z), u2h(a.z), q);
    q = __hfma2(u2h(a.w), u2h(a.w), q);
    q = __hfma2(u2h(b.x), u2h(b.x), q);
    q = __hfma2(u2h(b.y), u2h(b.y), q);
    q = __hfma2(u2h(b.z), u2h(b.z), q);
    q = __hfma2(u2h(b.w), u2h(b.w), q);
    float2 f = __half22float2(q);
    return f.x + f.y;
}

__device__ __forceinline__ float selu_f(float v) {
    const float scale = 1.0507009873554805f;
    const float alpha = 1.6732632423543772f;
    return v > 0.f ? scale * v : scale * alpha * (__expf(v) - 1.f);
}

__device__ __forceinline__ float grp16_sum(float v) {
    v += __shfl_xor_sync(0xffffffffu, v, 1);
    v += __shfl_xor_sync(0xffffffffu, v, 2);
    v += __shfl_xor_sync(0xffffffffu, v, 4);
    v += __shfl_xor_sync(0xffffffffu, v, 8);
    return v;
}

__device__ __forceinline__ float blockSum256s(float v, volatile float* sh8) {
    int t = threadIdx.x;
    #pragma unroll
    for (int d = 16; d > 0; d >>= 1) v += __shfl_xor_sync(0xffffffffu, v, d);
    if ((t & 31) == 0) sh8[t >> 5] = v;
    __syncthreads();
    float r = sh8[0] + sh8[1] + sh8[2] + sh8[3] + sh8[4] + sh8[5] + sh8[6] + sh8[7];
    __syncthreads();
    return r;
}

// ---------------- K1: s = softmax^2(xW+b), 4 nodes/warp + zeroing ---------
__global__ void __launch_bounds__(256) k_s(const float* __restrict__ x,
                                           const float* __restrict__ W,
                                           const float* __restrict__ bvec) {
    __shared__ float sWT[K_CL][132];
    __shared__ float xs[8][4][F_DIM];
    int t = threadIdx.x;
    int bid = blockIdx.x;                 // grid = 3200

    if (t < 64) ((uint4*)g_Mh)[bid * 64 + t] = make_uint4(0u,0u,0u,0u);
    if (bid < 128) ((float4*)g_ox)[bid * 256 + t] = make_float4(0.f,0.f,0.f,0.f);
    if (bid < 16) {
        int i = bid * 256 + t;
        ((float4*)g_adj)[i] = make_float4(0.f,0.f,0.f,0.f);
        ((float4*)g_cc)[i]  = make_float4(0.f,0.f,0.f,0.f);
    }
    if (bid == 0) {
        if (t < B_GRAPHS) { g_cnt_adj[t] = 0u; g_cnt_ox[t] = 0u; }
        if (t == 0) { g_num = 0.f; g_den = 0.f; g_ortho = 0.f; g_cnt = 0u; }
    }

    for (int i = t; i < F_DIM * K_CL; i += 256) {
        int j = i >> 4, k = i & 15;
        sWT[k][j] = W[i];
    }
    __syncthreads();

    int w = t >> 5, l = t & 31;
    int node0 = bid * 32 + w * 4;
    int k = l & 15, par = l >> 4;
    float bk = bvec[k];

    #pragma unroll
    for (int r = 0; r < 4; r++)
        ((float4*)xs[w][r])[l] = ((const float4*)x)[(node0 + r) * 32 + l];
    __syncwarp();

    float a0 = 0.f, a1 = 0.f, a2 = 0.f, a3 = 0.f;
    #pragma unroll
    for (int i = 0; i < 16; i++) {
        int ch = 2 * i + par;
        float4 wv = *(const float4*)&sWT[k][ch * 4];
        float4 x0 = ((const float4*)xs[w][0])[ch];
        float4 x1 = ((const float4*)xs[w][1])[ch];
        float4 x2 = ((const float4*)xs[w][2])[ch];
        float4 x3 = ((const float4*)xs[w][3])[ch];
        a0 = fmaf(x0.x, wv.x, a0); a0 = fmaf(x0.y, wv.y, a0);
        a0 = fmaf(x0.z, wv.z, a0); a0 = fmaf(x0.w, wv.w, a0);
        a1 = fmaf(x1.x, wv.x, a1); a1 = fmaf(x1.y, wv.y, a1);
        a1 = fmaf(x1.z, wv.z, a1); a1 = fmaf(x1.w, wv.w, a1);
        a2 = fmaf(x2.x, wv.x, a2); a2 = fmaf(x2.y, wv.y, a2);
        a2 = fmaf(x2.z, wv.z, a2); a2 = fmaf(x2.w, wv.w, a2);
        a3 = fmaf(x3.x, wv.x, a3); a3 = fmaf(x3.y, wv.y, a3);
        a3 = fmaf(x3.z, wv.z, a3); a3 = fmaf(x3.w, wv.w, a3);
    }
    float acc[4] = {a0, a1, a2, a3};
    #pragma unroll
    for (int r = 0; r < 4; r++) {
        float v = acc[r];
        v += __shfl_xor_sync(0xffffffffu, v, 16);
        v += bk;
        float e = __expf(v);
        float s1 = __fdividef(e, grp16_sum(e));
        e = __expf(s1);
        float s2 = __fdividef(e, grp16_sum(e));
        if (l < 16) {
            g_s [(node0 + r) * K_CL + l] = s2;
            g_sh[(node0 + r) * K_CL + l] = __float2half_rn(s2);
        }
    }
}

// ---------------- K2: [0,512) OX(+SELU), [512,6912) EDGE ------------------
// OX is DRAM/FMA-bound, EDGE is LTS/L1tex-bound: complementary pipes.
__global__ void __launch_bounds__(256) k_edge_ox(const float* __restrict__ x,
                                                 const float* __restrict__ ew,
                                                 const int* __restrict__ esrc,
                                                 const int* __restrict__ edst,
                                                 float* __restrict__ out) {
    __shared__ float sx_sh[CHUNK_X][K_CL];
    __shared__ float dsh[8];
    __shared__ int win;
    int t = threadIdx.x;

    if (blockIdx.x < OX_BLOCKS) {
        // ======== OX branch: 8 blocks/graph, 200 nodes ========
        int bo = blockIdx.x;
        int b = bo >> 3;
        int part = bo & 7;
        int base = b * NODES_PER_G + part * NPART_X;
        int f = t & 127, half = t >> 7;
        float accx[8] = {0.f,0.f,0.f,0.f,0.f,0.f,0.f,0.f};

        for (int c = 0; c < NPART_X / CHUNK_X; c++) {   // 5 chunks of 40 nodes
            __syncthreads();
            if (t < CHUNK_X * 4) {
                int node = t >> 2, p = t & 3;
                ((float4*)sx_sh[node])[p] = ((const float4*)g_s)[(base + c * CHUNK_X + node) * 4 + p];
            }
            __syncthreads();
            #pragma unroll 8
            for (int n = 0; n < CHUNK_X; n++) {
                float xv = __ldg(x + (base + c * CHUNK_X + n) * F_DIM + f);
                const float4* s4 = (const float4*)sx_sh[n];
                float4 sa = s4[half * 2], sb = s4[half * 2 + 1];
                accx[0] = fmaf(sa.x, xv, accx[0]);
                accx[1] = fmaf(sa.y, xv, accx[1]);
                accx[2] = fmaf(sa.z, xv, accx[2]);
                accx[3] = fmaf(sa.w, xv, accx[3]);
                accx[4] = fmaf(sb.x, xv, accx[4]);
                accx[5] = fmaf(sb.y, xv, accx[5]);
                accx[6] = fmaf(sb.z, xv, accx[6]);
                accx[7] = fmaf(sb.w, xv, accx[7]);
            }
        }
        #pragma unroll
        for (int kk = 0; kk < 8; kk++) {
            int kcol = half * 8 + kk;
            red1(&g_ox[(b * K_CL + kcol) * F_DIM + f], accx[kk]);
        }
        // last of the 8 OX blocks applies SELU for this graph
        __threadfence();
        __syncthreads();
        if (t == 0) {
            unsigned int old = atomicAdd(&g_cnt_ox[b], 1u);
            win = (old == SPLIT_X - 1);
        }
        __syncthreads();
        if (!win) return;
        __threadfence();
        #pragma unroll
        for (int q = 0; q < 8; q++) {
            int i = b * 2048 + q * 256 + t;
            out[i] = selu_f(__ldcg(&g_ox[i]));
        }
        return;
    }

    // ======== EDGE branch ========
    int i = (blockIdx.x - OX_BLOCKS) * 256 + t;
    int2 s2 = ((const int2*)esrc)[i];
    int2 d2 = ((const int2*)edst)[i];
    float2 w2 = ((const float2*)ew)[i];

    const uint4* p0 = (const uint4*)(g_sh + d2.x * K_CL);
    const uint4* p1 = (const uint4*)(g_sh + d2.y * K_CL);
    uint4 a0 = p0[0], b0 = p0[1];
    uint4 a1 = p1[0], b1 = p1[1];

    float den = w2.x * ssq16(a0, b0) + w2.y * ssq16(a1, b1);

    __half2 wx = __float2half2_rn(w2.x);
    __half2 wy = __float2half2_rn(w2.y);

    __half* mp0 = g_Mh + s2.x * K_CL;
    __half* mp1 = g_Mh + s2.y * K_CL;
    red4h(mp0,     h2m(a0.x, wx), h2m(a0.y, wx), h2m(a0.z, wx), h2m(a0.w, wx));
    red4h(mp0 + 8, h2m(b0.x, wx), h2m(b0.y, wx), h2m(b0.z, wx), h2m(b0.w, wx));
    red4h(mp1,     h2m(a1.x, wy), h2m(a1.y, wy), h2m(a1.z, wy), h2m(a1.w, wy));
    red4h(mp1 + 8, h2m(b1.x, wy), h2m(b1.y, wy), h2m(b1.z, wy), h2m(b1.w, wy));

    #pragma unroll
    for (int d = 16; d > 0; d >>= 1) den += __shfl_xor_sync(0xffffffffu, den, d);
    if ((t & 31) == 0) dsh[t >> 5] = den;
    __syncthreads();
    if (t == 0) {
        float v = 0.f;
        #pragma unroll
        for (int q = 0; q < 8; q++) v += dsh[q];
        red1(&g_den, v);
    }
}

// ---------------- K3: adj+CC + per-graph finalize + scalars ---------------
__global__ void __launch_bounds__(256) k_adj(float* __restrict__ out) {
    __shared__ float s_sh[CHUNK_A][K_CL];
    __shared__ float M_sh[CHUNK_A][K_CL];
    __shared__ float sh8[8];
    __shared__ float dpool[K_CL];
    __shared__ int win;
    int t = threadIdx.x;

    int b = blockIdx.x >> 4;
    int part = blockIdx.x & 15;
    int base = b * NODES_PER_G + part * NPART_A;
    int k1 = t >> 4, k2 = t & 15;

    float acc_adj = 0.f, acc_cc = 0.f;

    for (int c = 0; c < NPART_A / CHUNK_A; c++) {
        __syncthreads();
        if (t < 80) {
            int node = t >> 2, p = t & 3;
            int gi = base + c * CHUNK_A + node;
            ((float4*)s_sh[node])[p] = ((const float4*)g_s)[gi * 4 + p];
        } else if (t < 120) {
            int q = t - 80;
            int node = q >> 1, p = q & 1;
            int gi = base + c * CHUNK_A + node;
            uint4 h = ((const uint4*)g_Mh)[gi * 2 + p];
            float2 f0 = __half22float2(*(__half2*)&h.x);
            float2 f1 = __half22float2(*(__half2*)&h.y);
            float2 f2 = __half22float2(*(__half2*)&h.z);
            float2 f3 = __half22float2(*(__half2*)&h.w);
            float* mp = &M_sh[node][p * 8];
            mp[0] = f0.x; mp[1] = f0.y; mp[2] = f1.x; mp[3] = f1.y;
            mp[4] = f2.x; mp[5] = f2.y; mp[6] = f3.x; mp[7] = f3.y;
        }
        __syncthreads();
        #pragma unroll
        for (int n = 0; n < CHUNK_A; n++) {
            float sk1 = s_sh[n][k1];
            acc_adj = fmaf(sk1, M_sh[n][k2], acc_adj);
            acc_cc  = fmaf(sk1, s_sh[n][k2], acc_cc);
        }
    }
    red1(&g_adj[b * 256 + t], acc_adj);
    red1(&g_cc [b * 256 + t], acc_cc);

    // per-graph finalize by the last-arriving block
    __threadfence();
    __syncthreads();
    if (t == 0) {
        unsigned int old = atomicAdd(&g_cnt_adj[b], 1u);
        win = (old == SPLIT_A - 1);
    }
    __syncthreads();
    if (!win) return;
    __threadfence();

    float adj = __ldcg(&g_adj[b * 256 + t]);
    float cc  = __ldcg(&g_cc [b * 256 + t]);

    float tr = blockSum256s((k1 == k2) ? adj : 0.f, sh8);
    if (t == 0) red1(&g_num, tr);

    float nrm2 = blockSum256s(cc * cc, sh8);
    float nrm = sqrtf(nrm2);
    float diff = cc / nrm - ((k1 == k2) ? 0.25f : 0.f);
    float dsum = blockSum256s(diff * diff, sh8);
    if (t == 0) red1(&g_ortho, sqrtf(dsum));

    float am = (k1 == k2) ? 0.f : adj;
    float rs = grp16_sum(am);
    float dp = sqrtf(rs) + 1e-12f;
    if (k2 == 0) dpool[k1] = dp;
    __syncthreads();
    out[B_GRAPHS * K_CL * F_DIM + b * 256 + t] = am / (dp * dpool[k2]);

    // global scalars by the last-finishing graph
    __threadfence();
    __syncthreads();
    if (t == 0) {
        unsigned int old = atomicAdd(&g_cnt, 1u);
        if (old == B_GRAPHS - 1) {
            __threadfence();
            int off = B_GRAPHS * K_CL * F_DIM + B_GRAPHS * K_CL * K_CL;
            float num = __ldcg(&g_num);
            float den = __ldcg(&g_den);
            float ort = __ldcg(&g_ortho);
            out[off + 0] = -num / den;
            out[off + 1] = ort * (1.0f / (float)B_GRAPHS);
        }
    }
}

// ---------------- launch ----------------
extern "C" void kernel_launch(void* const* d_in, const int* in_sizes, int n_in,
                              void* d_out, int out_size) {
    const float* x    = (const float*)d_in[0];
    const float* W    = (const float*)d_in[1];
    const float* bv   = (const float*)d_in[2];
    const float* ew   = (const float*)d_in[3];
    const int*   esrc = (const int*)d_in[4];
    const int*   edst = (const int*)d_in[5];
    float* out = (float*)d_out;

    k_s      <<<N_NODES / 32, 256>>>(x, W, bv);                        // 1
    k_edge_ox<<<OX_BLOCKS + EDGE_BLOCKS, 256>>>(x, ew, esrc, edst, out); // 2 -> ncu
    k_adj    <<<ADJ_BLOCKS, 256>>>(out);                               // 3
}

// round 15
// speedup vs baseline: 2.6890x; 1.0593x over previous
#include <cuda_runtime.h>
#include <cuda_fp16.h>
#include <cstdint>

#define B_GRAPHS 64
#define NODES_PER_G 1600
#define N_NODES (B_GRAPHS * NODES_PER_G)   // 102400
#define F_DIM 128
#define K_CL 16
#define E_EDGES (N_NODES * 32)             // 3276800
#define SPLIT_A 16
#define NPART_A (NODES_PER_G / SPLIT_A)    // 100
#define CHUNK_A 20
#define SPLIT_X 8
#define NPART_X (NODES_PER_G / SPLIT_X)    // 200
#define CHUNK_X 40
#define EDGE_BLOCKS (E_EDGES / 512)        // 6400
#define ADJ_BLOCKS (B_GRAPHS * SPLIT_A)    // 1024
#define OX_BLOCKS (B_GRAPHS * SPLIT_X)     // 512

// ---------------- device scratch ----------------
__device__ __align__(16) float g_s[N_NODES * K_CL];      // fp32 s (6.55 MB)
__device__ __align__(32) __half g_sh[N_NODES * K_CL];    // fp16 s copy (3.28 MB)
__device__ __align__(32) __half g_Mh[N_NODES * K_CL];    // fp16 M accumulator (3.28 MB)
__device__ float g_adj[B_GRAPHS * K_CL * K_CL];
__device__ float g_cc[B_GRAPHS * K_CL * K_CL];
__device__ __align__(16) float g_ox[B_GRAPHS * K_CL * F_DIM];
__device__ float g_num;
__device__ float g_den;
__device__ float g_ortho;
__device__ unsigned int g_cnt;
__device__ unsigned int g_cnt_adj[B_GRAPHS];
__device__ unsigned int g_cnt_ox[B_GRAPHS];

// ---------------- helpers ----------------
__device__ __forceinline__ void red1(float* p, float a) {
    asm volatile("red.global.add.f32 [%0], %1;" :: "l"(p), "f"(a) : "memory");
}
__device__ __forceinline__ void red4h(__half* p, uint32_t r0, uint32_t r1,
                                      uint32_t r2, uint32_t r3) {
    asm volatile("red.global.add.noftz.v4.f16x2 [%0], {%1,%2,%3,%4};"
                 :: "l"(p), "r"(r0), "r"(r1), "r"(r2), "r"(r3) : "memory");
}
__device__ __forceinline__ __half2 u2h(uint32_t v) { return *(__half2*)&v; }
__device__ __forceinline__ uint32_t h2m(uint32_t v, __half2 w) {
    __half2 h = __hmul2(u2h(v), w);
    return *(uint32_t*)&h;
}
__device__ __forceinline__ float ssq16(uint4 a, uint4 b) {
    __half2 q = __hmul2(u2h(a.x), u2h(a.x));
    q = __hfma2(u2h(a.y), u2h(a.y), q);
    q = __hfma2(u2h(a.z), u2h(a.z), q);
    q = __hfma2(u2h(a.w), u2h(a.w), q);
    q = __hfma2(u2h(b.x), u2h(b.x), q);
    q = __hfma2(u2h(b.y), u2h(b.y), q);
    q = __hfma2(u2h(b.z), u2h(b.z), q);
    q = __hfma2(u2h(b.w), u2h(b.w), q);
    float2 f = __half22float2(q);
    return f.x + f.y;
}

__device__ __forceinline__ float selu_f(float v) {
    const float scale = 1.0507009873554805f;
    const float alpha = 1.6732632423543772f;
    return v > 0.f ? scale * v : scale * alpha * (__expf(v) - 1.f);
}

__device__ __forceinline__ float grp16_sum(float v) {
    v += __shfl_xor_sync(0xffffffffu, v, 1);
    v += __shfl_xor_sync(0xffffffffu, v, 2);
    v += __shfl_xor_sync(0xffffffffu, v, 4);
    v += __shfl_xor_sync(0xffffffffu, v, 8);
    return v;
}

__device__ __forceinline__ float blockSum256s(float v, volatile float* sh8) {
    int t = threadIdx.x;
    #pragma unroll
    for (int d = 16; d > 0; d >>= 1) v += __shfl_xor_sync(0xffffffffu, v, d);
    if ((t & 31) == 0) sh8[t >> 5] = v;
    __syncthreads();
    float r = sh8[0] + sh8[1] + sh8[2] + sh8[3] + sh8[4] + sh8[5] + sh8[6] + sh8[7];
    __syncthreads();
    return r;
}

// ---------------- tf32 mma helpers ----------------
__device__ __forceinline__ uint32_t f2tf32(float f) {
    uint32_t r;
    asm("cvt.rna.tf32.f32 %0, %1;" : "=r"(r) : "f"(f));
    return r;
}
__device__ __forceinline__ void mma_tf32(float* d,
                                         uint32_t a0, uint32_t a1, uint32_t a2, uint32_t a3,
                                         uint32_t b0, uint32_t b1) {
    asm volatile("mma.sync.aligned.m16n8k8.row.col.f32.tf32.tf32.f32 "
                 "{%0,%1,%2,%3}, {%4,%5,%6,%7}, {%8,%9}, {%0,%1,%2,%3};"
                 : "+f"(d[0]), "+f"(d[1]), "+f"(d[2]), "+f"(d[3])
                 : "r"(a0), "r"(a1), "r"(a2), "r"(a3), "r"(b0), "r"(b1));
}

// fast double-softmax over 4 values held by each of 4 lanes in a group (16 cols)
__device__ __forceinline__ void srow(int node, float v0, float v1, float v2, float v3) {
    float e0 = __expf(v0), e1 = __expf(v1), e2 = __expf(v2), e3 = __expf(v3);
    float s = e0 + e1 + e2 + e3;
    s += __shfl_xor_sync(0xffffffffu, s, 1);
    s += __shfl_xor_sync(0xffffffffu, s, 2);
    float r = __fdividef(1.f, s);
    float p0 = e0 * r, p1 = e1 * r, p2 = e2 * r, p3 = e3 * r;
    e0 = __expf(p0); e1 = __expf(p1); e2 = __expf(p2); e3 = __expf(p3);
    s = e0 + e1 + e2 + e3;
    s += __shfl_xor_sync(0xffffffffu, s, 1);
    s += __shfl_xor_sync(0xffffffffu, s, 2);
    r = __fdividef(1.f, s);
    float f0 = e0 * r, f1 = e1 * r, f2 = e2 * r, f3 = e3 * r;
    int q = threadIdx.x & 3;
    float2* ps = (float2*)(g_s + node * K_CL + 2 * q);
    ps[0] = make_float2(f0, f1);
    ps[4] = make_float2(f2, f3);          // cols +8
    __half2* ph = (__half2*)(g_sh + node * K_CL + 2 * q);
    ph[0] = __floats2half2_rn(f0, f1);
    ph[4] = __floats2half2_rn(f2, f3);
}

// ---------------- K1: s = softmax^2(xW+b) via tf32 MMA + zeroing ----------
// grid = 800, block = 256; warp handles a 16-node tile
__global__ void __launch_bounds__(256) k_s(const float* __restrict__ x,
                                           const float* __restrict__ W,
                                           const float* __restrict__ bvec) {
    __shared__ uint32_t sWB[F_DIM * 17];   // W pre-converted to tf32, padded stride 17
    int t = threadIdx.x;
    int bid = blockIdx.x;                  // grid = 800

    // folded zeroing: 800*256 = 204800 uint4 covers g_Mh exactly
    ((uint4*)g_Mh)[bid * 256 + t] = make_uint4(0u,0u,0u,0u);
    if (bid < 128) ((float4*)g_ox)[bid * 256 + t] = make_float4(0.f,0.f,0.f,0.f);
    if (bid < 16) {
        int i = bid * 256 + t;
        ((float4*)g_adj)[i] = make_float4(0.f,0.f,0.f,0.f);
        ((float4*)g_cc)[i]  = make_float4(0.f,0.f,0.f,0.f);
    }
    if (bid == 0) {
        if (t < B_GRAPHS) { g_cnt_adj[t] = 0u; g_cnt_ox[t] = 0u; }
        if (t == 0) { g_num = 0.f; g_den = 0.f; g_ortho = 0.f; g_cnt = 0u; }
    }

    // stage W as tf32 bits
    for (int i = t; i < F_DIM * K_CL; i += 256) {
        int j = i >> 4, k = i & 15;
        sWB[j * 17 + k] = f2tf32(W[i]);
    }
    __syncthreads();

    int w = t >> 5, lane = t & 31;
    int g = lane >> 2, q = lane & 3;
    int node0 = bid * 128 + w * 16;

    const float* p0 = x + (node0 + g) * F_DIM + q;
    const float* p1 = p0 + 8 * F_DIM;

    float acc0[4] = {0.f,0.f,0.f,0.f};
    float acc1[4] = {0.f,0.f,0.f,0.f};

    #pragma unroll
    for (int ks = 0; ks < 16; ks++) {
        int j0 = ks * 8;
        uint32_t a0 = f2tf32(__ldg(p0 + j0));
        uint32_t a1 = f2tf32(__ldg(p1 + j0));
        uint32_t a2 = f2tf32(__ldg(p0 + j0 + 4));
        uint32_t a3 = f2tf32(__ldg(p1 + j0 + 4));
        uint32_t b00 = sWB[(j0 + q) * 17 + g];
        uint32_t b10 = sWB[(j0 + q + 4) * 17 + g];
        uint32_t b01 = sWB[(j0 + q) * 17 + g + 8];
        uint32_t b11 = sWB[(j0 + q + 4) * 17 + g + 8];
        mma_tf32(acc0, a0, a1, a2, a3, b00, b10);
        mma_tf32(acc1, a0, a1, a2, a3, b01, b11);
    }

    // bias for this thread's 4 columns {2q, 2q+1, 2q+8, 2q+9}
    float bk0 = bvec[2 * q], bk1 = bvec[2 * q + 1];
    float bk2 = bvec[2 * q + 8], bk3 = bvec[2 * q + 9];

    // row g: (acc0[0], acc0[1], acc1[0], acc1[1]); row g+8: (acc0[2], acc0[3], acc1[2], acc1[3])
    srow(node0 + g,     acc0[0] + bk0, acc0[1] + bk1, acc1[0] + bk2, acc1[1] + bk3);
    srow(node0 + g + 8, acc0[2] + bk0, acc0[3] + bk1, acc1[2] + bk2, acc1[3] + bk3);
}

// ---------------- K2: [0,512) OX(+SELU), [512,6912) EDGE ------------------
__global__ void __launch_bounds__(256) k_edge_ox(const float* __restrict__ x,
                                                 const float* __restrict__ ew,
                                                 const int* __restrict__ esrc,
                                                 const int* __restrict__ edst,
                                                 float* __restrict__ out) {
    __shared__ float sx_sh[CHUNK_X][K_CL];
    __shared__ float dsh[8];
    __shared__ int win;
    int t = threadIdx.x;

    if (blockIdx.x < OX_BLOCKS) {
        int bo = blockIdx.x;
        int b = bo >> 3;
        int part = bo & 7;
        int base = b * NODES_PER_G + part * NPART_X;
        int f = t & 127, half = t >> 7;
        float accx[8] = {0.f,0.f,0.f,0.f,0.f,0.f,0.f,0.f};

        for (int c = 0; c < NPART_X / CHUNK_X; c++) {   // 5 chunks of 40 nodes
            __syncthreads();
            if (t < CHUNK_X * 4) {
                int node = t >> 2, p = t & 3;
                ((float4*)sx_sh[node])[p] = ((const float4*)g_s)[(base + c * CHUNK_X + node) * 4 + p];
            }
            __syncthreads();
            #pragma unroll 8
            for (int n = 0; n < CHUNK_X; n++) {
                float xv = __ldg(x + (base + c * CHUNK_X + n) * F_DIM + f);
                const float4* s4 = (const float4*)sx_sh[n];
                float4 sa = s4[half * 2], sb = s4[half * 2 + 1];
                accx[0] = fmaf(sa.x, xv, accx[0]);
                accx[1] = fmaf(sa.y, xv, accx[1]);
                accx[2] = fmaf(sa.z, xv, accx[2]);
                accx[3] = fmaf(sa.w, xv, accx[3]);
                accx[4] = fmaf(sb.x, xv, accx[4]);
                accx[5] = fmaf(sb.y, xv, accx[5]);
                accx[6] = fmaf(sb.z, xv, accx[6]);
                accx[7] = fmaf(sb.w, xv, accx[7]);
            }
        }
        #pragma unroll
        for (int kk = 0; kk < 8; kk++) {
            int kcol = half * 8 + kk;
            red1(&g_ox[(b * K_CL + kcol) * F_DIM + f], accx[kk]);
        }
        __threadfence();
        __syncthreads();
        if (t == 0) {
            unsigned int old = atomicAdd(&g_cnt_ox[b], 1u);
            win = (old == SPLIT_X - 1);
        }
        __syncthreads();
        if (!win) return;
        __threadfence();
        #pragma unroll
        for (int qq = 0; qq < 8; qq++) {
            int i = b * 2048 + qq * 256 + t;
            out[i] = selu_f(__ldcg(&g_ox[i]));
        }
        return;
    }

    // ======== EDGE branch ========
    int i = (blockIdx.x - OX_BLOCKS) * 256 + t;
    int2 s2 = ((const int2*)esrc)[i];
    int2 d2 = ((const int2*)edst)[i];
    float2 w2 = ((const float2*)ew)[i];

    const uint4* p0 = (const uint4*)(g_sh + d2.x * K_CL);
    const uint4* p1 = (const uint4*)(g_sh + d2.y * K_CL);
    uint4 a0 = p0[0], b0 = p0[1];
    uint4 a1 = p1[0], b1 = p1[1];

    float den = w2.x * ssq16(a0, b0) + w2.y * ssq16(a1, b1);

    __half2 wx = __float2half2_rn(w2.x);
    __half2 wy = __float2half2_rn(w2.y);

    __half* mp0 = g_Mh + s2.x * K_CL;
    __half* mp1 = g_Mh + s2.y * K_CL;
    red4h(mp0,     h2m(a0.x, wx), h2m(a0.y, wx), h2m(a0.z, wx), h2m(a0.w, wx));
    red4h(mp0 + 8, h2m(b0.x, wx), h2m(b0.y, wx), h2m(b0.z, wx), h2m(b0.w, wx));
    red4h(mp1,     h2m(a1.x, wy), h2m(a1.y, wy), h2m(a1.z, wy), h2m(a1.w, wy));
    red4h(mp1 + 8, h2m(b1.x, wy), h2m(b1.y, wy), h2m(b1.z, wy), h2m(b1.w, wy));

    #pragma unroll
    for (int d = 16; d > 0; d >>= 1) den += __shfl_xor_sync(0xffffffffu, den, d);
    if ((t & 31) == 0) dsh[t >> 5] = den;
    __syncthreads();
    if (t == 0) {
        float v = 0.f;
        #pragma unroll
        for (int qq = 0; qq < 8; qq++) v += dsh[qq];
        red1(&g_den, v);
    }
}

// ---------------- K3: adj+CC + per-graph finalize + scalars ---------------
__global__ void __launch_bounds__(256) k_adj(float* __restrict__ out) {
    __shared__ float s_sh[CHUNK_A][K_CL];
    __shared__ float M_sh[CHUNK_A][K_CL];
    __shared__ float sh8[8];
    __shared__ float dpool[K_CL];
    __shared__ int win;
    int t = threadIdx.x;

    int b = blockIdx.x >> 4;
    int part = blockIdx.x & 15;
    int base = b * NODES_PER_G + part * NPART_A;
    int k1 = t >> 4, k2 = t & 15;

    float acc_adj = 0.f, acc_cc = 0.f;

    for (int c = 0; c < NPART_A / CHUNK_A; c++) {
        __syncthreads();
        if (t < 80) {
            int node = t >> 2, p = t & 3;
            int gi = base + c * CHUNK_A + node;
            ((float4*)s_sh[node])[p] = ((const float4*)g_s)[gi * 4 + p];
        } else if (t < 120) {
            int q = t - 80;
            int node = q >> 1, p = q & 1;
            int gi = base + c * CHUNK_A + node;
            uint4 h = ((const uint4*)g_Mh)[gi * 2 + p];
            float2 f0 = __half22float2(*(__half2*)&h.x);
            float2 f1 = __half22float2(*(__half2*)&h.y);
            float2 f2 = __half22float2(*(__half2*)&h.z);
            float2 f3 = __half22float2(*(__half2*)&h.w);
            float* mp = &M_sh[node][p * 8];
            mp[0] = f0.x; mp[1] = f0.y; mp[2] = f1.x; mp[3] = f1.y;
            mp[4] = f2.x; mp[5] = f2.y; mp[6] = f3.x; mp[7] = f3.y;
        }
        __syncthreads();
        #pragma unroll
        for (int n = 0; n < CHUNK_A; n++) {
            float sk1 = s_sh[n][k1];
            acc_adj = fmaf(sk1, M_sh[n][k2], acc_adj);
            acc_cc  = fmaf(sk1, s_sh[n][k2], acc_cc);
        }
    }
    red1(&g_adj[b * 256 + t], acc_adj);
    red1(&g_cc [b * 256 + t], acc_cc);

    __threadfence();
    __syncthreads();
    if (t == 0) {
        unsigned int old = atomicAdd(&g_cnt_adj[b], 1u);
        win = (old == SPLIT_A - 1);
    }
    __syncthreads();
    if (!win) return;
    __threadfence();

    float adj = __ldcg(&g_adj[b * 256 + t]);
    float cc  = __ldcg(&g_cc [b * 256 + t]);

    float tr = blockSum256s((k1 == k2) ? adj : 0.f, sh8);
    if (t == 0) red1(&g_num, tr);

    float nrm2 = blockSum256s(cc * cc, sh8);
    float nrm = sqrtf(nrm2);
    float diff = cc / nrm - ((k1 == k2) ? 0.25f : 0.f);
    float dsum = blockSum256s(diff * diff, sh8);
    if (t == 0) red1(&g_ortho, sqrtf(dsum));

    float am = (k1 == k2) ? 0.f : adj;
    float rs = grp16_sum(am);
    float dp = sqrtf(rs) + 1e-12f;
    if (k2 == 0) dpool[k1] = dp;
    __syncthreads();
    out[B_GRAPHS * K_CL * F_DIM + b * 256 + t] = am / (dp * dpool[k2]);

    __threadfence();
    __syncthreads();
    if (t == 0) {
        unsigned int old = atomicAdd(&g_cnt, 1u);
        if (old == B_GRAPHS - 1) {
            __threadfence();
            int off = B_GRAPHS * K_CL * F_DIM + B_GRAPHS * K_CL * K_CL;
            float num = __ldcg(&g_num);
            float den = __ldcg(&g_den);
            float ort = __ldcg(&g_ortho);
            out[off + 0] = -num / den;
            out[off + 1] = ort * (1.0f / (float)B_GRAPHS);
        }
    }
}

// ---------------- launch ----------------
extern "C" void kernel_launch(void* const* d_in, const int* in_sizes, int n_in,
                              void* d_out, int out_size) {
    const float* x    = (const float*)d_in[0];
    const float* W    = (const float*)d_in[1];
    const float* bv   = (const float*)d_in[2];
    const float* ew   = (const float*)d_in[3];
    const int*   esrc = (const int*)d_in[4];
    const int*   edst = (const int*)d_in[5];
    float* out = (float*)d_out;

    k_s      <<<N_NODES / 128, 256>>>(x, W, bv);                       // 1 -> ncu
    k_edge_ox<<<OX_BLOCKS + EDGE_BLOCKS, 256>>>(x, ew, esrc, edst, out); // 2
    k_adj    <<<ADJ_BLOCKS, 256>>>(out);                               // 3
}

// round 16
// speedup vs baseline: 2.9417x; 1.0940x over previous
#include <cuda_runtime.h>
#include <cuda_fp16.h>
#include <cstdint>

#define B_GRAPHS 64
#define NODES_PER_G 1600
#define N_NODES (B_GRAPHS * NODES_PER_G)   // 102400
#define F_DIM 128
#define K_CL 16
#define E_EDGES (N_NODES * 32)             // 3276800
#define SPLIT_A 16
#define NPART_A (NODES_PER_G / SPLIT_A)    // 100
#define CHUNK_A 20
#define SPLIT_X 8
#define NPART_X (NODES_PER_G / SPLIT_X)    // 200
#define CHUNK_X 40
#define EDGE_BLOCKS (E_EDGES / 512)        // 6400
#define ADJ_BLOCKS (B_GRAPHS * SPLIT_A)    // 1024
#define OX_BLOCKS (B_GRAPHS * SPLIT_X)     // 512

// ---------------- device scratch ----------------
__device__ __align__(16) float g_s[N_NODES * K_CL];      // fp32 s (6.55 MB)
__device__ __align__(32) __half g_sh[N_NODES * K_CL];    // fp16 s copy (3.28 MB)
__device__ __align__(32) __half g_Mh[N_NODES * K_CL];    // fp16 M accumulator (3.28 MB)
__device__ float g_adj[B_GRAPHS * K_CL * K_CL];
__device__ float g_cc[B_GRAPHS * K_CL * K_CL];
__device__ __align__(16) float g_ox[B_GRAPHS * K_CL * F_DIM];
__device__ float g_num;
__device__ float g_den;
__device__ float g_ortho;
__device__ unsigned int g_cnt;
__device__ unsigned int g_cnt_adj[B_GRAPHS];
__device__ unsigned int g_cnt_ox[B_GRAPHS];

// ---------------- helpers ----------------
__device__ __forceinline__ void red1(float* p, float a) {
    asm volatile("red.global.add.f32 [%0], %1;" :: "l"(p), "f"(a) : "memory");
}
__device__ __forceinline__ void red4h(__half* p, uint32_t r0, uint32_t r1,
                                      uint32_t r2, uint32_t r3) {
    asm volatile("red.global.add.noftz.v4.f16x2 [%0], {%1,%2,%3,%4};"
                 :: "l"(p), "r"(r0), "r"(r1), "r"(r2), "r"(r3) : "memory");
}
__device__ __forceinline__ __half2 u2h(uint32_t v) { return *(__half2*)&v; }
__device__ __forceinline__ uint32_t h2m(uint32_t v, __half2 w) {
    __half2 h = __hmul2(u2h(v), w);
    return *(uint32_t*)&h;
}
__device__ __forceinline__ float ssq16(uint4 a, uint4 b) {
    __half2 q = __hmul2(u2h(a.x), u2h(a.x));
    q = __hfma2(u2h(a.y), u2h(a.y), q);
    q = __hfma2(u2h(a.z), u2h(a.z), q);
    q = __hfma2(u2h(a.w), u2h(a.w), q);
    q = __hfma2(u2h(b.x), u2h(b.x), q);
    q = __hfma2(u2h(b.y), u2h(b.y), q);
    q = __hfma2(u2h(b.z), u2h(b.z), q);
    q = __hfma2(u2h(b.w), u2h(b.w), q);
    float2 f = __half22float2(q);
    return f.x + f.y;
}

__device__ __forceinline__ float selu_f(float v) {
    const float scale = 1.0507009873554805f;
    const float alpha = 1.6732632423543772f;
    return v > 0.f ? scale * v : scale * alpha * (__expf(v) - 1.f);
}

__device__ __forceinline__ float grp16_sum(float v) {
    v += __shfl_xor_sync(0xffffffffu, v, 1);
    v += __shfl_xor_sync(0xffffffffu, v, 2);
    v += __shfl_xor_sync(0xffffffffu, v, 4);
    v += __shfl_xor_sync(0xffffffffu, v, 8);
    return v;
}

__device__ __forceinline__ float blockSum256s(float v, volatile float* sh8) {
    int t = threadIdx.x;
    #pragma unroll
    for (int d = 16; d > 0; d >>= 1) v += __shfl_xor_sync(0xffffffffu, v, d);
    if ((t & 31) == 0) sh8[t >> 5] = v;
    __syncthreads();
    float r = sh8[0] + sh8[1] + sh8[2] + sh8[3] + sh8[4] + sh8[5] + sh8[6] + sh8[7];
    __syncthreads();
    return r;
}

// ---------------- tf32 mma helpers ----------------
__device__ __forceinline__ uint32_t f2tf32(float f) {
    uint32_t r;
    asm("cvt.rna.tf32.f32 %0, %1;" : "=r"(r) : "f"(f));
    return r;
}
__device__ __forceinline__ void mma_tf32(float* d,
                                         uint32_t a0, uint32_t a1, uint32_t a2, uint32_t a3,
                                         uint32_t b0, uint32_t b1) {
    asm volatile("mma.sync.aligned.m16n8k8.row.col.f32.tf32.tf32.f32 "
                 "{%0,%1,%2,%3}, {%4,%5,%6,%7}, {%8,%9}, {%0,%1,%2,%3};"
                 : "+f"(d[0]), "+f"(d[1]), "+f"(d[2]), "+f"(d[3])
                 : "r"(a0), "r"(a1), "r"(a2), "r"(a3), "r"(b0), "r"(b1));
}

// fast double-softmax over 4 values held by each of 4 lanes in a group (16 cols)
__device__ __forceinline__ void srow(int node, float v0, float v1, float v2, float v3) {
    float e0 = __expf(v0), e1 = __expf(v1), e2 = __expf(v2), e3 = __expf(v3);
    float s = e0 + e1 + e2 + e3;
    s += __shfl_xor_sync(0xffffffffu, s, 1);
    s += __shfl_xor_sync(0xffffffffu, s, 2);
    float r = __fdividef(1.f, s);
    float p0 = e0 * r, p1 = e1 * r, p2 = e2 * r, p3 = e3 * r;
    e0 = __expf(p0); e1 = __expf(p1); e2 = __expf(p2); e3 = __expf(p3);
    s = e0 + e1 + e2 + e3;
    s += __shfl_xor_sync(0xffffffffu, s, 1);
    s += __shfl_xor_sync(0xffffffffu, s, 2);
    r = __fdividef(1.f, s);
    float f0 = e0 * r, f1 = e1 * r, f2 = e2 * r, f3 = e3 * r;
    int q = threadIdx.x & 3;
    float2* ps = (float2*)(g_s + node * K_CL + 2 * q);
    ps[0] = make_float2(f0, f1);
    ps[4] = make_float2(f2, f3);          // cols +8
    __half2* ph = (__half2*)(g_sh + node * K_CL + 2 * q);
    ph[0] = __floats2half2_rn(f0, f1);
    ph[4] = __floats2half2_rn(f2, f3);
}

// ---------------- K1: s = softmax^2(xW+b) via tf32 MMA + zeroing ----------
__global__ void __launch_bounds__(256) k_s(const float* __restrict__ x,
                                           const float* __restrict__ W,
                                           const float* __restrict__ bvec) {
    __shared__ uint32_t sWB[F_DIM * 17];   // W pre-converted to tf32, padded stride 17
    int t = threadIdx.x;
    int bid = blockIdx.x;                  // grid = 800

    // folded zeroing: 800*256 = 204800 uint4 covers g_Mh exactly
    ((uint4*)g_Mh)[bid * 256 + t] = make_uint4(0u,0u,0u,0u);
    if (bid < 128) ((float4*)g_ox)[bid * 256 + t] = make_float4(0.f,0.f,0.f,0.f);
    if (bid < 16) {
        int i = bid * 256 + t;
        ((float4*)g_adj)[i] = make_float4(0.f,0.f,0.f,0.f);
        ((float4*)g_cc)[i]  = make_float4(0.f,0.f,0.f,0.f);
    }
    if (bid == 0) {
        if (t < B_GRAPHS) { g_cnt_adj[t] = 0u; g_cnt_ox[t] = 0u; }
        if (t == 0) { g_num = 0.f; g_den = 0.f; g_ortho = 0.f; g_cnt = 0u; }
    }

    for (int i = t; i < F_DIM * K_CL; i += 256) {
        int j = i >> 4, k = i & 15;
        sWB[j * 17 + k] = f2tf32(W[i]);
    }
    __syncthreads();

    int w = t >> 5, lane = t & 31;
    int g = lane >> 2, q = lane & 3;
    int node0 = bid * 128 + w * 16;

    const float* p0 = x + (node0 + g) * F_DIM + q;
    const float* p1 = p0 + 8 * F_DIM;

    float acc0[4] = {0.f,0.f,0.f,0.f};
    float acc1[4] = {0.f,0.f,0.f,0.f};

    #pragma unroll
    for (int ks = 0; ks < 16; ks++) {
        int j0 = ks * 8;
        uint32_t a0 = f2tf32(__ldg(p0 + j0));
        uint32_t a1 = f2tf32(__ldg(p1 + j0));
        uint32_t a2 = f2tf32(__ldg(p0 + j0 + 4));
        uint32_t a3 = f2tf32(__ldg(p1 + j0 + 4));
        uint32_t b00 = sWB[(j0 + q) * 17 + g];
        uint32_t b10 = sWB[(j0 + q + 4) * 17 + g];
        uint32_t b01 = sWB[(j0 + q) * 17 + g + 8];
        uint32_t b11 = sWB[(j0 + q + 4) * 17 + g + 8];
        mma_tf32(acc0, a0, a1, a2, a3, b00, b10);
        mma_tf32(acc1, a0, a1, a2, a3, b01, b11);
    }

    float bk0 = bvec[2 * q], bk1 = bvec[2 * q + 1];
    float bk2 = bvec[2 * q + 8], bk3 = bvec[2 * q + 9];

    srow(node0 + g,     acc0[0] + bk0, acc0[1] + bk1, acc1[0] + bk2, acc1[1] + bk3);
    srow(node0 + g + 8, acc0[2] + bk0, acc0[3] + bk1, acc1[2] + bk2, acc1[3] + bk3);
}

// ---------------- K2: [0,512) OX via tf32 MMA (+SELU), [512,6912) EDGE ----
__global__ void __launch_bounds__(256) k_edge_ox(const float* __restrict__ x,
                                                 const float* __restrict__ ew,
                                                 const int* __restrict__ esrc,
                                                 const int* __restrict__ edst,
                                                 float* __restrict__ out) {
    __shared__ uint32_t xs_u[CHUNK_X][130];   // x chunk as tf32 (20.8 KB)
    __shared__ uint32_t ss_u[CHUNK_X][17];    // s chunk as tf32 (2.7 KB)
    __shared__ float dsh[8];
    __shared__ int win;
    int t = threadIdx.x;

    if (blockIdx.x < OX_BLOCKS) {
        // ======== OX branch: out_x partial = S_part^T X_part via MMA ========
        int bo = blockIdx.x;
        int b = bo >> 3;
        int part = bo & 7;
        int base = b * NODES_PER_G + part * NPART_X;
        int w = t >> 5, lane = t & 31;
        int g = lane >> 2, q = lane & 3;
        int n0w = w * 16;                 // warp's 16-feature slice

        float acc[2][4] = {{0.f,0.f,0.f,0.f},{0.f,0.f,0.f,0.f}};

        for (int c = 0; c < NPART_X / CHUNK_X; c++) {   // 5 chunks of 40 nodes
            __syncthreads();
            // stage x chunk: 40 nodes x 128 feats (1280 float4), tf32-converted
            for (int i = t; i < CHUNK_X * 32; i += 256) {
                int node = i >> 5, p = i & 31;
                float4 v = ((const float4*)x)[(base + c * CHUNK_X + node) * 32 + p];
                uint32_t* d = &xs_u[node][p * 4];
                d[0] = f2tf32(v.x); d[1] = f2tf32(v.y);
                d[2] = f2tf32(v.z); d[3] = f2tf32(v.w);
            }
            // stage s chunk: 40 x 16 (160 float4)
            if (t < CHUNK_X * 4) {
                int node = t >> 2, p = t & 3;
                float4 v = ((const float4*)g_s)[(base + c * CHUNK_X + node) * 4 + p];
                uint32_t* d = &ss_u[node][p * 4];
                d[0] = f2tf32(v.x); d[1] = f2tf32(v.y);
                d[2] = f2tf32(v.z); d[3] = f2tf32(v.w);
            }
            __syncthreads();
            #pragma unroll
            for (int ks = 0; ks < CHUNK_X / 8; ks++) {   // 5 k-steps of 8 nodes
                int k0 = ks * 8;
                // A = S^T (16 kcl x 8 nodes)
                uint32_t a0 = ss_u[k0 + q][g];
                uint32_t a1 = ss_u[k0 + q][g + 8];
                uint32_t a2 = ss_u[k0 + q + 4][g];
                uint32_t a3 = ss_u[k0 + q + 4][g + 8];
                // B = X (8 nodes x 8 feats), two n-tiles
                uint32_t b00 = xs_u[k0 + q][n0w + g];
                uint32_t b01 = xs_u[k0 + q + 4][n0w + g];
                uint32_t b10 = xs_u[k0 + q][n0w + 8 + g];
                uint32_t b11 = xs_u[k0 + q + 4][n0w + 8 + g];
                mma_tf32(acc[0], a0, a1, a2, a3, b00, b01);
                mma_tf32(acc[1], a0, a1, a2, a3, b10, b11);
            }
        }
        // writeback: D[kcl][feat]; thread (g,q) holds (g,2q),(g,2q+1),(g+8,2q),(g+8,2q+1)
        #pragma unroll
        for (int j = 0; j < 2; j++) {
            int nb = n0w + j * 8;
            red1(&g_ox[(b * K_CL + g)     * F_DIM + nb + 2 * q],     acc[j][0]);
            red1(&g_ox[(b * K_CL + g)     * F_DIM + nb + 2 * q + 1], acc[j][1]);
            red1(&g_ox[(b * K_CL + g + 8) * F_DIM + nb + 2 * q],     acc[j][2]);
            red1(&g_ox[(b * K_CL + g + 8) * F_DIM + nb + 2 * q + 1], acc[j][3]);
        }
        // last of the 8 OX blocks applies SELU for this graph
        __threadfence();
        __syncthreads();
        if (t == 0) {
            unsigned int old = atomicAdd(&g_cnt_ox[b], 1u);
            win = (old == SPLIT_X - 1);
        }
        __syncthreads();
        if (!win) return;
        __threadfence();
        #pragma unroll
        for (int qq = 0; qq < 8; qq++) {
            int i = b * 2048 + qq * 256 + t;
            out[i] = selu_f(__ldcg(&g_ox[i]));
        }
        return;
    }

    // ======== EDGE branch ========
    int i = (blockIdx.x - OX_BLOCKS) * 256 + t;
    int2 s2 = ((const int2*)esrc)[i];
    int2 d2 = ((const int2*)edst)[i];
    float2 w2 = ((const float2*)ew)[i];

    const uint4* p0 = (const uint4*)(g_sh + d2.x * K_CL);
    const uint4* p1 = (const uint4*)(g_sh + d2.y * K_CL);
    uint4 a0 = p0[0], b0 = p0[1];
    uint4 a1 = p1[0], b1 = p1[1];

    float den = w2.x * ssq16(a0, b0) + w2.y * ssq16(a1, b1);

    __half2 wx = __float2half2_rn(w2.x);
    __half2 wy = __float2half2_rn(w2.y);

    __half* mp0 = g_Mh + s2.x * K_CL;
    __half* mp1 = g_Mh + s2.y * K_CL;
    red4h(mp0,     h2m(a0.x, wx), h2m(a0.y, wx), h2m(a0.z, wx), h2m(a0.w, wx));
    red4h(mp0 + 8, h2m(b0.x, wx), h2m(b0.y, wx), h2m(b0.z, wx), h2m(b0.w, wx));
    red4h(mp1,     h2m(a1.x, wy), h2m(a1.y, wy), h2m(a1.z, wy), h2m(a1.w, wy));
    red4h(mp1 + 8, h2m(b1.x, wy), h2m(b1.y, wy), h2m(b1.z, wy), h2m(b1.w, wy));

    #pragma unroll
    for (int d = 16; d > 0; d >>= 1) den += __shfl_xor_sync(0xffffffffu, den, d);
    if ((t & 31) == 0) dsh[t >> 5] = den;
    __syncthreads();
    if (t == 0) {
        float v = 0.f;
        #pragma unroll
        for (int qq = 0; qq < 8; qq++) v += dsh[qq];
        red1(&g_den, v);
    }
}

// ---------------- K3: adj+CC + per-graph finalize + scalars ---------------
__global__ void __launch_bounds__(256) k_adj(float* __restrict__ out) {
    __shared__ float s_sh[CHUNK_A][K_CL];
    __shared__ float M_sh[CHUNK_A][K_CL];
    __shared__ float sh8[8];
    __shared__ float dpool[K_CL];
    __shared__ int win;
    int t = threadIdx.x;

    int b = blockIdx.x >> 4;
    int part = blockIdx.x & 15;
    int base = b * NODES_PER_G + part * NPART_A;
    int k1 = t >> 4, k2 = t & 15;

    float acc_adj = 0.f, acc_cc = 0.f;

    for (int c = 0; c < NPART_A / CHUNK_A; c++) {
        __syncthreads();
        if (t < 80) {
            int node = t >> 2, p = t & 3;
            int gi = base + c * CHUNK_A + node;
            ((float4*)s_sh[node])[p] = ((const float4*)g_s)[gi * 4 + p];
        } else if (t < 120) {
            int q = t - 80;
            int node = q >> 1, p = q & 1;
            int gi = base + c * CHUNK_A + node;
            uint4 h = ((const uint4*)g_Mh)[gi * 2 + p];
            float2 f0 = __half22float2(*(__half2*)&h.x);
            float2 f1 = __half22float2(*(__half2*)&h.y);
            float2 f2 = __half22float2(*(__half2*)&h.z);
            float2 f3 = __half22float2(*(__half2*)&h.w);
            float* mp = &M_sh[node][p * 8];
            mp[0] = f0.x; mp[1] = f0.y; mp[2] = f1.x; mp[3] = f1.y;
            mp[4] = f2.x; mp[5] = f2.y; mp[6] = f3.x; mp[7] = f3.y;
        }
        __syncthreads();
        #pragma unroll
        for (int n = 0; n < CHUNK_A; n++) {
            float sk1 = s_sh[n][k1];
            acc_adj = fmaf(sk1, M_sh[n][k2], acc_adj);
            acc_cc  = fmaf(sk1, s_sh[n][k2], acc_cc);
        }
    }
    red1(&g_adj[b * 256 + t], acc_adj);
    red1(&g_cc [b * 256 + t], acc_cc);

    __threadfence();
    __syncthreads();
    if (t == 0) {
        unsigned int old = atomicAdd(&g_cnt_adj[b], 1u);
        win = (old == SPLIT_A - 1);
    }
    __syncthreads();
    if (!win) return;
    __threadfence();

    float adj = __ldcg(&g_adj[b * 256 + t]);
    float cc  = __ldcg(&g_cc [b * 256 + t]);

    float tr = blockSum256s((k1 == k2) ? adj : 0.f, sh8);
    if (t == 0) red1(&g_num, tr);

    float nrm2 = blockSum256s(cc * cc, sh8);
    float nrm = sqrtf(nrm2);
    float diff = cc / nrm - ((k1 == k2) ? 0.25f : 0.f);
    float dsum = blockSum256s(diff * diff, sh8);
    if (t == 0) red1(&g_ortho, sqrtf(dsum));

    float am = (k1 == k2) ? 0.f : adj;
    float rs = grp16_sum(am);
    float dp = sqrtf(rs) + 1e-12f;
    if (k2 == 0) dpool[k1] = dp;
    __syncthreads();
    out[B_GRAPHS * K_CL * F_DIM + b * 256 + t] = am / (dp * dpool[k2]);

    __threadfence();
    __syncthreads();
    if (t == 0) {
        unsigned int old = atomicAdd(&g_cnt, 1u);
        if (old == B_GRAPHS - 1) {
            __threadfence();
            int off = B_GRAPHS * K_CL * F_DIM + B_GRAPHS * K_CL * K_CL;
            float num = __ldcg(&g_num);
            float den = __ldcg(&g_den);
            float ort = __ldcg(&g_ortho);
            out[off + 0] = -num / den;
            out[off + 1] = ort * (1.0f / (float)B_GRAPHS);
        }
    }
}

// ---------------- launch ----------------
extern "C" void kernel_launch(void* const* d_in, const int* in_sizes, int n_in,
                              void* d_out, int out_size) {
    const float* x    = (const float*)d_in[0];
    const float* W    = (const float*)d_in[1];
    const float* bv   = (const float*)d_in[2];
    const float* ew   = (const float*)d_in[3];
    const int*   esrc = (const int*)d_in[4];
    const int*   edst = (const int*)d_in[5];
    float* out = (float*)d_out;

    k_s      <<<N_NODES / 128, 256>>>(x, W, bv);                       // 1
    k_edge_ox<<<OX_BLOCKS + EDGE_BLOCKS, 256>>>(x, ew, esrc, edst, out); // 2 -> ncu
    k_adj    <<<ADJ_BLOCKS, 256>>>(out);                               // 3
}

// round 17
// speedup vs baseline: 3.0812x; 1.0474x over previous
#include <cuda_runtime.h>
#include <cuda_fp16.h>
#include <cstdint>

#define B_GRAPHS 64
#define NODES_PER_G 1600
#define N_NODES (B_GRAPHS * NODES_PER_G)   // 102400
#define F_DIM 128
#define K_CL 16
#define E_EDGES (N_NODES * 32)             // 3276800
#define SPLIT_A 16
#define NPART_A (NODES_PER_G / SPLIT_A)    // 100
#define CHUNK_A 20
#define SPLIT_X 8
#define NPART_X (NODES_PER_G / SPLIT_X)    // 200
#define CHUNK_X 40
#define EDGE_BLOCKS (E_EDGES / 512)        // 6400
#define ADJ_BLOCKS (B_GRAPHS * SPLIT_A)    // 1024
#define OX_BLOCKS (B_GRAPHS * SPLIT_X)     // 512

// ---------------- device scratch ----------------
__device__ __align__(16) float g_s[N_NODES * K_CL];      // fp32 s (6.55 MB)
__device__ __align__(32) __half g_sh[N_NODES * K_CL];    // fp16 s copy (3.28 MB)
__device__ __align__(32) __half g_Mh[N_NODES * K_CL];    // fp16 M accumulator (3.28 MB)
__device__ float g_adj[B_GRAPHS * K_CL * K_CL];
__device__ float g_cc[B_GRAPHS * K_CL * K_CL];
__device__ __align__(16) float g_ox[B_GRAPHS * K_CL * F_DIM];
__device__ float g_num;
__device__ float g_den;
__device__ float g_ortho;
__device__ unsigned int g_cnt;
__device__ unsigned int g_cnt_adj[B_GRAPHS];
__device__ unsigned int g_cnt_ox[B_GRAPHS];

// ---------------- helpers ----------------
__device__ __forceinline__ void red1(float* p, float a) {
    asm volatile("red.global.add.f32 [%0], %1;" :: "l"(p), "f"(a) : "memory");
}
__device__ __forceinline__ void red4h(__half* p, uint32_t r0, uint32_t r1,
                                      uint32_t r2, uint32_t r3) {
    asm volatile("red.global.add.noftz.v4.f16x2 [%0], {%1,%2,%3,%4};"
                 :: "l"(p), "r"(r0), "r"(r1), "r"(r2), "r"(r3) : "memory");
}
__device__ __forceinline__ __half2 u2h(uint32_t v) { return *(__half2*)&v; }
__device__ __forceinline__ uint32_t h2m(uint32_t v, __half2 w) {
    __half2 h = __hmul2(u2h(v), w);
    return *(uint32_t*)&h;
}
__device__ __forceinline__ float ssq16(uint4 a, uint4 b) {
    __half2 q = __hmul2(u2h(a.x), u2h(a.x));
    q = __hfma2(u2h(a.y), u2h(a.y), q);
    q = __hfma2(u2h(a.z), u2h(a.z), q);
    q = __hfma2(u2h(a.w), u2h(a.w), q);
    q = __hfma2(u2h(b.x), u2h(b.x), q);
    q = __hfma2(u2h(b.y), u2h(b.y), q);
    q = __hfma2(u2h(b.z), u2h(b.z), q);
    q = __hfma2(u2h(b.w), u2h(b.w), q);
    float2 f = __half22float2(q);
    return f.x + f.y;
}

__device__ __forceinline__ float selu_f(float v) {
    const float scale = 1.0507009873554805f;
    const float alpha = 1.6732632423543772f;
    return v > 0.f ? scale * v : scale * alpha * (__expf(v) - 1.f);
}

__device__ __forceinline__ float grp16_sum(float v) {
    v += __shfl_xor_sync(0xffffffffu, v, 1);
    v += __shfl_xor_sync(0xffffffffu, v, 2);
    v += __shfl_xor_sync(0xffffffffu, v, 4);
    v += __shfl_xor_sync(0xffffffffu, v, 8);
    return v;
}

__device__ __forceinline__ float blockSum256s(float v, volatile float* sh8) {
    int t = threadIdx.x;
    #pragma unroll
    for (int d = 16; d > 0; d >>= 1) v += __shfl_xor_sync(0xffffffffu, v, d);
    if ((t & 31) == 0) sh8[t >> 5] = v;
    __syncthreads();
    float r = sh8[0] + sh8[1] + sh8[2] + sh8[3] + sh8[4] + sh8[5] + sh8[6] + sh8[7];
    __syncthreads();
    return r;
}

// ---------------- tf32 mma helpers ----------------
__device__ __forceinline__ uint32_t f2tf32(float f) {
    uint32_t r;
    asm("cvt.rna.tf32.f32 %0, %1;" : "=r"(r) : "f"(f));
    return r;
}
__device__ __forceinline__ void mma_tf32(float* d,
                                         uint32_t a0, uint32_t a1, uint32_t a2, uint32_t a3,
                                         uint32_t b0, uint32_t b1) {
    asm volatile("mma.sync.aligned.m16n8k8.row.col.f32.tf32.tf32.f32 "
                 "{%0,%1,%2,%3}, {%4,%5,%6,%7}, {%8,%9}, {%0,%1,%2,%3};"
                 : "+f"(d[0]), "+f"(d[1]), "+f"(d[2]), "+f"(d[3])
                 : "r"(a0), "r"(a1), "r"(a2), "r"(a3), "r"(b0), "r"(b1));
}

// fast double-softmax over 4 values held by each of 4 lanes in a group (16 cols)
__device__ __forceinline__ void srow(int node, float v0, float v1, float v2, float v3) {
    float e0 = __expf(v0), e1 = __expf(v1), e2 = __expf(v2), e3 = __expf(v3);
    float s = e0 + e1 + e2 + e3;
    s += __shfl_xor_sync(0xffffffffu, s, 1);
    s += __shfl_xor_sync(0xffffffffu, s, 2);
    float r = __fdividef(1.f, s);
    float p0 = e0 * r, p1 = e1 * r, p2 = e2 * r, p3 = e3 * r;
    e0 = __expf(p0); e1 = __expf(p1); e2 = __expf(p2); e3 = __expf(p3);
    s = e0 + e1 + e2 + e3;
    s += __shfl_xor_sync(0xffffffffu, s, 1);
    s += __shfl_xor_sync(0xffffffffu, s, 2);
    r = __fdividef(1.f, s);
    float f0 = e0 * r, f1 = e1 * r, f2 = e2 * r, f3 = e3 * r;
    int q = threadIdx.x & 3;
    float2* ps = (float2*)(g_s + node * K_CL + 2 * q);
    ps[0] = make_float2(f0, f1);
    ps[4] = make_float2(f2, f3);          // cols +8
    __half2* ph = (__half2*)(g_sh + node * K_CL + 2 * q);
    ph[0] = __floats2half2_rn(f0, f1);
    ph[4] = __floats2half2_rn(f2, f3);
}

// ---------------- K1: s = softmax^2(xW+b) via tf32 MMA + zeroing ----------
// x staged through SMEM with coalesced LDG.128; A frags from conflict-free LDS
__global__ void __launch_bounds__(256) k_s(const float* __restrict__ x,
                                           const float* __restrict__ W,
                                           const float* __restrict__ bvec) {
    __shared__ uint32_t sWB[F_DIM * 17];   // W as tf32, padded stride 17
    __shared__ uint32_t sx[8][16 * 68];    // per-warp 16 nodes x 64 feats (stride 68)
    int t = threadIdx.x;
    int bid = blockIdx.x;                  // grid = 800

    // folded zeroing: 800*256 = 204800 uint4 covers g_Mh exactly
    ((uint4*)g_Mh)[bid * 256 + t] = make_uint4(0u,0u,0u,0u);
    if (bid < 128) ((float4*)g_ox)[bid * 256 + t] = make_float4(0.f,0.f,0.f,0.f);
    if (bid < 16) {
        int i = bid * 256 + t;
        ((float4*)g_adj)[i] = make_float4(0.f,0.f,0.f,0.f);
        ((float4*)g_cc)[i]  = make_float4(0.f,0.f,0.f,0.f);
    }
    if (bid == 0) {
        if (t < B_GRAPHS) { g_cnt_adj[t] = 0u; g_cnt_ox[t] = 0u; }
        if (t == 0) { g_num = 0.f; g_den = 0.f; g_ortho = 0.f; g_cnt = 0u; }
    }

    for (int i = t; i < F_DIM * K_CL; i += 256) {
        int j = i >> 4, k = i & 15;
        sWB[j * 17 + k] = f2tf32(W[i]);
    }
    __syncthreads();

    int w = t >> 5, lane = t & 31;
    int g = lane >> 2, q = lane & 3;
    int node0 = bid * 128 + w * 16;
    uint32_t* mysx = sx[w];

    float acc0[4] = {0.f,0.f,0.f,0.f};
    float acc1[4] = {0.f,0.f,0.f,0.f};

    #pragma unroll
    for (int h = 0; h < 2; h++) {          // two K=64 phases
        __syncwarp();
        // stage: 16 nodes x 64 feats, coalesced float4, converted to tf32
        #pragma unroll
        for (int i = 0; i < 8; i++) {
            int linear = i * 32 + lane;
            int row = linear >> 4;         // 0..15
            int c4 = linear & 15;          // float4 col within half
            float4 v = __ldg((const float4*)x + (node0 + row) * 32 + h * 16 + c4);
            uint4 u = make_uint4(f2tf32(v.x), f2tf32(v.y), f2tf32(v.z), f2tf32(v.w));
            *(uint4*)&mysx[row * 68 + c4 * 4] = u;
        }
        __syncwarp();
        #pragma unroll
        for (int ks = 0; ks < 8; ks++) {
            int j0 = ks * 8;
            int jg = h * 64 + j0;
            uint32_t a0 = mysx[g * 68 + j0 + q];            // bank 4g+q: conflict-free
            uint32_t a1 = mysx[(g + 8) * 68 + j0 + q];
            uint32_t a2 = mysx[g * 68 + j0 + q + 4];
            uint32_t a3 = mysx[(g + 8) * 68 + j0 + q + 4];
            uint32_t b00 = sWB[(jg + q) * 17 + g];
            uint32_t b10 = sWB[(jg + q + 4) * 17 + g];
            uint32_t b01 = sWB[(jg + q) * 17 + g + 8];
            uint32_t b11 = sWB[(jg + q + 4) * 17 + g + 8];
            mma_tf32(acc0, a0, a1, a2, a3, b00, b10);
            mma_tf32(acc1, a0, a1, a2, a3, b01, b11);
        }
    }

    float bk0 = bvec[2 * q], bk1 = bvec[2 * q + 1];
    float bk2 = bvec[2 * q + 8], bk3 = bvec[2 * q + 9];

    srow(node0 + g,     acc0[0] + bk0, acc0[1] + bk1, acc1[0] + bk2, acc1[1] + bk3);
    srow(node0 + g + 8, acc0[2] + bk0, acc0[3] + bk1, acc1[2] + bk2, acc1[3] + bk3);
}

// ---------------- K2: [0,512) OX via tf32 MMA (+SELU), [512,6912) EDGE ----
__global__ void __launch_bounds__(256) k_edge_ox(const float* __restrict__ x,
                                                 const float* __restrict__ ew,
                                                 const int* __restrict__ esrc,
                                                 const int* __restrict__ edst,
                                                 float* __restrict__ out) {
    __shared__ uint32_t xs_u[CHUNK_X][130];   // x chunk as tf32 (20.8 KB)
    __shared__ uint32_t ss_u[CHUNK_X][17];    // s chunk as tf32 (2.7 KB)
    __shared__ float dsh[8];
    __shared__ int win;
    int t = threadIdx.x;

    if (blockIdx.x < OX_BLOCKS) {
        int bo = blockIdx.x;
        int b = bo >> 3;
        int part = bo & 7;
        int base = b * NODES_PER_G + part * NPART_X;
        int w = t >> 5, lane = t & 31;
        int g = lane >> 2, q = lane & 3;
        int n0w = w * 16;

        float acc[2][4] = {{0.f,0.f,0.f,0.f},{0.f,0.f,0.f,0.f}};

        for (int c = 0; c < NPART_X / CHUNK_X; c++) {
            __syncthreads();
            for (int i = t; i < CHUNK_X * 32; i += 256) {
                int node = i >> 5, p = i & 31;
                float4 v = ((const float4*)x)[(base + c * CHUNK_X + node) * 32 + p];
                uint32_t* d = &xs_u[node][p * 4];
                d[0] = f2tf32(v.x); d[1] = f2tf32(v.y);
                d[2] = f2tf32(v.z); d[3] = f2tf32(v.w);
            }
            if (t < CHUNK_X * 4) {
                int node = t >> 2, p = t & 3;
                float4 v = ((const float4*)g_s)[(base + c * CHUNK_X + node) * 4 + p];
                uint32_t* d = &ss_u[node][p * 4];
                d[0] = f2tf32(v.x); d[1] = f2tf32(v.y);
                d[2] = f2tf32(v.z); d[3] = f2tf32(v.w);
            }
            __syncthreads();
            #pragma unroll
            for (int ks = 0; ks < CHUNK_X / 8; ks++) {
                int k0 = ks * 8;
                uint32_t a0 = ss_u[k0 + q][g];
                uint32_t a1 = ss_u[k0 + q][g + 8];
                uint32_t a2 = ss_u[k0 + q + 4][g];
                uint32_t a3 = ss_u[k0 + q + 4][g + 8];
                uint32_t b00 = xs_u[k0 + q][n0w + g];
                uint32_t b01 = xs_u[k0 + q + 4][n0w + g];
                uint32_t b10 = xs_u[k0 + q][n0w + 8 + g];
                uint32_t b11 = xs_u[k0 + q + 4][n0w + 8 + g];
                mma_tf32(acc[0], a0, a1, a2, a3, b00, b01);
                mma_tf32(acc[1], a0, a1, a2, a3, b10, b11);
            }
        }
        #pragma unroll
        for (int j = 0; j < 2; j++) {
            int nb = n0w + j * 8;
            red1(&g_ox[(b * K_CL + g)     * F_DIM + nb + 2 * q],     acc[j][0]);
            red1(&g_ox[(b * K_CL + g)     * F_DIM + nb + 2 * q + 1], acc[j][1]);
            red1(&g_ox[(b * K_CL + g + 8) * F_DIM + nb + 2 * q],     acc[j][2]);
            red1(&g_ox[(b * K_CL + g + 8) * F_DIM + nb + 2 * q + 1], acc[j][3]);
        }
        __threadfence();
        __syncthreads();
        if (t == 0) {
            unsigned int old = atomicAdd(&g_cnt_ox[b], 1u);
            win = (old == SPLIT_X - 1);
        }
        __syncthreads();
        if (!win) return;
        __threadfence();
        #pragma unroll
        for (int qq = 0; qq < 8; qq++) {
            int i = b * 2048 + qq * 256 + t;
            out[i] = selu_f(__ldcg(&g_ox[i]));
        }
        return;
    }

    // ======== EDGE branch ========
    int i = (blockIdx.x - OX_BLOCKS) * 256 + t;
    int2 s2 = ((const int2*)esrc)[i];
    int2 d2 = ((const int2*)edst)[i];
    float2 w2 = ((const float2*)ew)[i];

    const uint4* p0 = (const uint4*)(g_sh + d2.x * K_CL);
    const uint4* p1 = (const uint4*)(g_sh + d2.y * K_CL);
    uint4 a0 = p0[0], b0 = p0[1];
    uint4 a1 = p1[0], b1 = p1[1];

    float den = w2.x * ssq16(a0, b0) + w2.y * ssq16(a1, b1);

    __half2 wx = __float2half2_rn(w2.x);
    __half2 wy = __float2half2_rn(w2.y);

    __half* mp0 = g_Mh + s2.x * K_CL;
    __half* mp1 = g_Mh + s2.y * K_CL;
    red4h(mp0,     h2m(a0.x, wx), h2m(a0.y, wx), h2m(a0.z, wx), h2m(a0.w, wx));
    red4h(mp0 + 8, h2m(b0.x, wx), h2m(b0.y, wx), h2m(b0.z, wx), h2m(b0.w, wx));
    red4h(mp1,     h2m(a1.x, wy), h2m(a1.y, wy), h2m(a1.z, wy), h2m(a1.w, wy));
    red4h(mp1 + 8, h2m(b1.x, wy), h2m(b1.y, wy), h2m(b1.z, wy), h2m(b1.w, wy));

    #pragma unroll
    for (int d = 16; d > 0; d >>= 1) den += __shfl_xor_sync(0xffffffffu, den, d);
    if ((t & 31) == 0) dsh[t >> 5] = den;
    __syncthreads();
    if (t == 0) {
        float v = 0.f;
        #pragma unroll
        for (int qq = 0; qq < 8; qq++) v += dsh[qq];
        red1(&g_den, v);
    }
}

// ---------------- K3: adj+CC + per-graph finalize + scalars ---------------
__global__ void __launch_bounds__(256) k_adj(float* __restrict__ out) {
    __shared__ float s_sh[CHUNK_A][K_CL];
    __shared__ float M_sh[CHUNK_A][K_CL];
    __shared__ float sh8[8];
    __shared__ float dpool[K_CL];
    __shared__ int win;
    int t = threadIdx.x;

    int b = blockIdx.x >> 4;
    int part = blockIdx.x & 15;
    int base = b * NODES_PER_G + part * NPART_A;
    int k1 = t >> 4, k2 = t & 15;

    float acc_adj = 0.f, acc_cc = 0.f;

    for (int c = 0; c < NPART_A / CHUNK_A; c++) {
        __syncthreads();
        if (t < 80) {
            int node = t >> 2, p = t & 3;
            int gi = base + c * CHUNK_A + node;
            ((float4*)s_sh[node])[p] = ((const float4*)g_s)[gi * 4 + p];
        } else if (t < 120) {
            int q = t - 80;
            int node = q >> 1, p = q & 1;
            int gi = base + c * CHUNK_A + node;
            uint4 h = ((const uint4*)g_Mh)[gi * 2 + p];
            float2 f0 = __half22float2(*(__half2*)&h.x);
            float2 f1 = __half22float2(*(__half2*)&h.y);
            float2 f2 = __half22float2(*(__half2*)&h.z);
            float2 f3 = __half22float2(*(__half2*)&h.w);
            float* mp = &M_sh[node][p * 8];
            mp[0] = f0.x; mp[1] = f0.y; mp[2] = f1.x; mp[3] = f1.y;
            mp[4] = f2.x; mp[5] = f2.y; mp[6] = f3.x; mp[7] = f3.y;
        }
        __syncthreads();
        #pragma unroll
        for (int n = 0; n < CHUNK_A; n++) {
            float sk1 = s_sh[n][k1];
            acc_adj = fmaf(sk1, M_sh[n][k2], acc_adj);
            acc_cc  = fmaf(sk1, s_sh[n][k2], acc_cc);
        }
    }
    red1(&g_adj[b * 256 + t], acc_adj);
    red1(&g_cc [b * 256 + t], acc_cc);

    __threadfence();
    __syncthreads();
    if (t == 0) {
        unsigned int old = atomicAdd(&g_cnt_adj[b], 1u);
        win = (old == SPLIT_A - 1);
    }
    __syncthreads();
    if (!win) return;
    __threadfence();

    float adj = __ldcg(&g_adj[b * 256 + t]);
    float cc  = __ldcg(&g_cc [b * 256 + t]);

    float tr = blockSum256s((k1 == k2) ? adj : 0.f, sh8);
    if (t == 0) red1(&g_num, tr);

    float nrm2 = blockSum256s(cc * cc, sh8);
    float nrm = sqrtf(nrm2);
    float diff = cc / nrm - ((k1 == k2) ? 0.25f : 0.f);
    float dsum = blockSum256s(diff * diff, sh8);
    if (t == 0) red1(&g_ortho, sqrtf(dsum));

    float am = (k1 == k2) ? 0.f : adj;
    float rs = grp16_sum(am);
    float dp = sqrtf(rs) + 1e-12f;
    if (k2 == 0) dpool[k1] = dp;
    __syncthreads();
    out[B_GRAPHS * K_CL * F_DIM + b * 256 + t] = am / (dp * dpool[k2]);

    __threadfence();
    __syncthreads();
    if (t == 0) {
        unsigned int old = atomicAdd(&g_cnt, 1u);
        if (old == B_GRAPHS - 1) {
            __threadfence();
            int off = B_GRAPHS * K_CL * F_DIM + B_GRAPHS * K_CL * K_CL;
            float num = __ldcg(&g_num);
            float den = __ldcg(&g_den);
            float ort = __ldcg(&g_ortho);
            out[off + 0] = -num / den;
            out[off + 1] = ort * (1.0f / (float)B_GRAPHS);
        }
    }
}

// ---------------- launch ----------------
extern "C" void kernel_launch(void* const* d_in, const int* in_sizes, int n_in,
                              void* d_out, int out_size) {
    const float* x    = (const float*)d_in[0];
    const float* W    = (const float*)d_in[1];
    const float* bv   = (const float*)d_in[2];
    const float* ew   = (const float*)d_in[3];
    const int*   esrc = (const int*)d_in[4];
    const int*   edst = (const int*)d_in[5];
    float* out = (float*)d_out;

    k_s      <<<N_NODES / 128, 256>>>(x, W, bv);                       // 1 -> ncu
    k_edge_ox<<<OX_BLOCKS + EDGE_BLOCKS, 256>>>(x, ew, esrc, edst, out); // 2
    k_adj    <<<ADJ_BLOCKS, 256>>>(out);                               // 3
}